// round 4
// baseline (speedup 1.0000x reference)
#include <cuda_runtime.h>
#include <cstdint>

#define NN 4096
typedef unsigned long long ull;

__device__ __align__(128) float  g_x[NN*66];
__device__ __align__(128) float  g_h[4*NN*80];
__device__ __align__(128) float  g_f1[4*NN];
__device__ __align__(128) float  g_f2[4*NN];
__device__ __align__(128) float2 g_pq[4*NN];
__device__ __align__(128) float4 g_jd[4*NN];
__device__ __align__(128) float  g_hcat[NN*264];
__device__ __align__(128) float  g_sub[NN*66];
__device__ __align__(128) float  g_u[NN*64];
__device__ __align__(128) float  g_part[4*NN*72];
__device__ __align__(128) unsigned g_mask[NN*128];

__device__ __forceinline__ void fma2(ull& d, ull a, ull b){
    asm("fma.rn.f32x2 %0, %1, %2, %0;" : "+l"(d) : "l"(a), "l"(b));
}
__device__ __forceinline__ ull dup2(float v){
    ull r; asm("mov.b64 %0, {%1, %1};" : "=l"(r) : "f"(v)); return r;
}
__device__ __forceinline__ float2 up2(ull v){
    float2 r; asm("mov.b64 {%0, %1}, %2;" : "=f"(r.x), "=f"(r.y) : "l"(v)); return r;
}
__device__ __forceinline__ void cpa16(void* d, const void* s){
    unsigned sd = (unsigned)__cvta_generic_to_shared(d);
    asm volatile("cp.async.ca.shared.global [%0],[%1],16;" :: "r"(sd), "l"(s));
}
#define CP_COMMIT() asm volatile("cp.async.commit_group;")
#define CP_WAIT(N)  asm volatile("cp.async.wait_group %0;"::"n"(N))

__global__ void __launch_bounds__(256) pack_mask_kernel(const int* __restrict__ adj, unsigned* __restrict__ mask){
    int idx = blockIdx.x*256 + threadIdx.x;
    const int4* p = (const int4*)(adj + (size_t)idx*32);
    unsigned m = 0;
#pragma unroll
    for (int q = 0; q < 8; q++){
        int4 v = p[q];
        m |= (v.x>0?1u:0u)<<(q*4+0); m |= (v.y>0?1u:0u)<<(q*4+1);
        m |= (v.z>0?1u:0u)<<(q*4+2); m |= (v.w>0?1u:0u)<<(q*4+3);
    }
    mask[idx] = m;
}

__global__ void __launch_bounds__(256) build_x1_kernel(const float* __restrict__ inputs, const float* __restrict__ hx, float* __restrict__ x){
    int idx = blockIdx.x*256 + threadIdx.x;
    if (idx >= NN*66) return;
    int i = idx/66, c = idx - i*66;
    x[idx] = (c < 2) ? inputs[i*2+c] : hx[i*64 + c-2];
}

// h = x @ W per head (stride-80 out, col66=1), + f1/f2/jd epilogue.
__global__ void __launch_bounds__(256) proj_kernel(const float* __restrict__ x, int Din,
    const float* __restrict__ W, const float* __restrict__ a1, const float* __restrict__ a2,
    float* __restrict__ ho, float* __restrict__ f1o, float* __restrict__ f2o, float4* __restrict__ jdo)
{
    __shared__ float Ws[66*66];
    __shared__ float xs[64*67];
    const int head = blockIdx.y;
    const int row0 = blockIdx.x*64;
    const int tid = threadIdx.x;
    W += (size_t)head*Din*66; a1 += head*66; a2 += head*66;
    const int r = tid>>2, part = tid&3;
    const int c0 = (part<2) ? part*17 : 34 + (part-2)*16;
    const int cnt = (part<2) ? 17 : 16;
    float acc[17];
#pragma unroll
    for (int c = 0; c < 17; c++) acc[c] = 0.f;
    for (int k0 = 0; k0 < Din; k0 += 66){
        __syncthreads();
        for (int idx = tid; idx < 66*66; idx += 256) Ws[idx] = W[(size_t)k0*66 + idx];
        for (int idx = tid; idx < 64*66; idx += 256){
            int rr = idx/66, kk = idx - rr*66;
            xs[rr*67+kk] = x[(size_t)(row0+rr)*Din + k0 + kk];
        }
        __syncthreads();
        for (int kk = 0; kk < 66; kk++){
            float xv = xs[r*67+kk];
            const float* wr = Ws + kk*66 + c0;
#pragma unroll
            for (int c = 0; c < 17; c++) if (c < cnt) acc[c] += xv*wr[c];
        }
    }
    float p1 = 0.f, p2 = 0.f;
#pragma unroll
    for (int c = 0; c < 17; c++) if (c < cnt){ p1 += acc[c]*a1[c0+c]; p2 += acc[c]*a2[c0+c]; }
    p1 += __shfl_xor_sync(~0u, p1, 1); p1 += __shfl_xor_sync(~0u, p1, 2);
    p2 += __shfl_xor_sync(~0u, p2, 1); p2 += __shfl_xor_sync(~0u, p2, 2);
    int row = row0 + r;
    if (part == 0){
        f1o[head*NN+row] = p1; f2o[head*NN+row] = p2;
        jdo[head*NN+row] = make_float4(p2, __expf(p2), __expf(0.2f*p2), 0.f);
    }
    float* hr = ho + (size_t)(head*NN+row)*80;
#pragma unroll
    for (int c = 0; c < 17; c++) if (c < cnt) hr[c0+c] = acc[c];
    if (part == 3){
        hr[66] = 1.0f;
#pragma unroll
        for (int c = 67; c < 80; c++) hr[c] = 0.f;
    }
}

// masked row-max of f2 + P/Q precompute. one warp per row.
template<int NH>
__global__ void __launch_bounds__(256) rowmax_pq_kernel(const float* __restrict__ f1b,
    const float* __restrict__ f2b, const unsigned* __restrict__ mask, float2* __restrict__ pqo)
{
    int row = blockIdx.x*8 + (threadIdx.x>>5);
    int lane = threadIdx.x & 31;
    float m[NH];
#pragma unroll
    for (int h = 0; h < NH; h++) m[h] = -3e38f;
    const unsigned* mrow = mask + (size_t)row*128;
#pragma unroll 4
    for (int k = 0; k < 128; k++){
        unsigned w = mrow[k];
        bool b = (w>>lane)&1u;
        int j = k*32 + lane;
#pragma unroll
        for (int h = 0; h < NH; h++){
            float v = f2b[h*NN + j];
            m[h] = fmaxf(m[h], b ? v : -3e38f);
        }
    }
#pragma unroll
    for (int h = 0; h < NH; h++){
        float v = m[h];
#pragma unroll
        for (int s = 16; s; s >>= 1) v = fmaxf(v, __shfl_xor_sync(~0u, v, s));
        if (lane == 0){
            float f1 = f1b[h*NN+row];
            float e = f1 + v;
            float M = fmaxf(e, 0.2f*e);
            pqo[h*NN+row] = make_float2(__expf(f1 - M), __expf(0.2f*f1 - M));
        }
    }
}

// fused masked softmax-attention aggregation, exp-factorized, cp.async pipelined.
__global__ void __launch_bounds__(256) agg_kernel(const float* __restrict__ hb,
    const float* __restrict__ f1b, const float2* __restrict__ pqb, const float4* __restrict__ jdb,
    const unsigned* __restrict__ mask, float* __restrict__ outp, int os, float* __restrict__ partp)
{
    __shared__ float h_lo[64*64];
    __shared__ float h_hi[64*16];
    __shared__ float4 jd_s[2][64];
    __shared__ float w_s[64*66];
    __shared__ float den_s[64];
    const int head = blockIdx.z;
    const int row0 = blockIdx.x*64;
    const int tid = threadIdx.x;
    const int T = 64/gridDim.y;
    const int t0 = blockIdx.y*T;
    const float* hsrc = hb + (size_t)head*NN*80;
    const float4* jds = jdb + head*NN;
    const int ar = tid&63, jh = tid>>6;
    const float f1r = f1b[head*NN + row0 + ar];
    const float2 pq = pqb[head*NN + row0 + ar];
    const int rg = tid>>3, cq = tid&7;
    ull aLo0[4] = {0,0,0,0}, aLo1[4] = {0,0,0,0}, aHi0 = 0, aHi1 = 0;

    if (tid < 64) cpa16(&jd_s[0][tid], &jds[t0*64 + tid]);
    CP_COMMIT();
    CP_WAIT(0);
    __syncthreads();

    int buf = 0;
    for (int t = t0; t < t0+T; t++){
        // prefetch h(t) (overlaps phase A)
#pragma unroll
        for (int q = 0; q < 5; q++){
            int idx = tid + q*256;
            int jr = idx/20, c4 = idx - jr*20;
            float* dst = (c4 < 16) ? &h_lo[jr*64 + c4*4] : &h_hi[jr*16 + (c4-16)*4];
            cpa16(dst, hsrc + (size_t)(t*64 + jr)*80 + c4*4);
        }
        CP_COMMIT();
        if (t+1 < t0+T && tid < 64) cpa16(&jd_s[buf^1][tid], &jds[(t+1)*64 + tid]);
        CP_COMMIT();
        // phase A: w = mask * (x>0 ? P*e^{f2} : Q*e^{0.2 f2})
        unsigned mw = mask[(size_t)(row0+ar)*128 + t*2 + (jh>>1)];
        int bs = (jh&1)*16;
#pragma unroll
        for (int k = 0; k < 16; k++){
            int j = jh*16 + k;
            float4 jd = jd_s[buf][j];
            float x = f1r + jd.x;
            bool pos = x > 0.f;
            float u = pos ? pq.x : pq.y;
            float v = pos ? jd.y : jd.z;
            float w = ((mw>>(bs+k))&1u) ? u*v : 0.f;
            w_s[j*66 + ar] = w;
        }
        CP_WAIT(1);
        __syncthreads();
        // phase B: acc += w * h (packed f32x2)
#pragma unroll 4
        for (int j = 0; j < 64; j++){
            float2 wp = *(const float2*)&w_s[j*66 + 2*rg];
            ull w0 = dup2(wp.x), w1 = dup2(wp.y);
            const ulonglong2* pl = (const ulonglong2*)&h_lo[j*64 + cq*8];
            ulonglong2 ha = pl[0], hc = pl[1];
            ull hh = *(const ull*)&h_hi[j*16 + cq*2];
            fma2(aLo0[0], w0, ha.x); fma2(aLo0[1], w0, ha.y);
            fma2(aLo0[2], w0, hc.x); fma2(aLo0[3], w0, hc.y);
            fma2(aLo1[0], w1, ha.x); fma2(aLo1[1], w1, ha.y);
            fma2(aLo1[2], w1, hc.x); fma2(aLo1[3], w1, hc.y);
            fma2(aHi0, w0, hh); fma2(aHi1, w1, hh);
        }
        __syncthreads();
        buf ^= 1;
    }

    if (partp){
        float* p0 = partp + ((size_t)blockIdx.y*NN + row0 + 2*rg)*72;
        float* p1 = p0 + 72;
#pragma unroll
        for (int q = 0; q < 4; q++){
            ((ull*)p0)[cq*4 + q] = aLo0[q];
            ((ull*)p1)[cq*4 + q] = aLo1[q];
        }
        if (cq == 0){ ((ull*)p0)[32] = aHi0; ((ull*)p1)[32] = aHi1; }
        if (cq == 1){ p0[66] = up2(aHi0).x; p1[66] = up2(aHi1).x; }
    } else {
        if (cq == 1){ den_s[2*rg] = up2(aHi0).x; den_s[2*rg+1] = up2(aHi1).x; }
        __syncthreads();
        float inv0 = 1.f/den_s[2*rg], inv1 = 1.f/den_s[2*rg+1];
        float* o0 = outp + (size_t)(row0 + 2*rg)*os + head*66;
        float* o1 = o0 + os;
#pragma unroll
        for (int q = 0; q < 4; q++){
            int c = cq*8 + 2*q;
            float2 a = up2(aLo0[q]), b = up2(aLo1[q]);
            float v;
            v = a.x*inv0; o0[c]   = fmaxf(v, 0.01f*v);
            v = a.y*inv0; o0[c+1] = fmaxf(v, 0.01f*v);
            v = b.x*inv1; o1[c]   = fmaxf(v, 0.01f*v);
            v = b.y*inv1; o1[c+1] = fmaxf(v, 0.01f*v);
        }
        if (cq == 0){
            float2 a = up2(aHi0), b = up2(aHi1);
            float v;
            v = a.x*inv0; o0[64] = fmaxf(v, 0.01f*v);
            v = a.y*inv0; o0[65] = fmaxf(v, 0.01f*v);
            v = b.x*inv1; o1[64] = fmaxf(v, 0.01f*v);
            v = b.y*inv1; o1[65] = fmaxf(v, 0.01f*v);
        }
    }
}

__global__ void __launch_bounds__(96) reduce_kernel(const float* __restrict__ part, float* __restrict__ out){
    int i = blockIdx.x, c = threadIdx.x;
    if (c >= 66) return;
    float num = 0.f, den = 0.f;
#pragma unroll
    for (int k = 0; k < 4; k++){
        const float* p = part + ((size_t)k*NN + i)*72;
        num += p[c]; den += p[66];
    }
    float v = num/den;
    out[i*66 + c] = fmaxf(v, 0.01f*v);
}

__global__ void __launch_bounds__(128) gate1_kernel(const float* __restrict__ sub,
    const float* __restrict__ hx, const float* __restrict__ W, const float* __restrict__ b,
    float* __restrict__ xout, float* __restrict__ uout)
{
    __shared__ float xs[66];
    int i = blockIdx.x, c = threadIdx.x;
    for (int k = c; k < 66; k += 128) xs[k] = sub[i*66+k];
    __syncthreads();
    float a = b[c];
    for (int k = 0; k < 66; k++) a += xs[k]*W[k*128+c];
    float v = 1.f/(1.f + __expf(-a));
    if (c < 64) xout[i*66 + 2 + c] = v*hx[i*64+c];
    else uout[i*64 + c - 64] = v;
}

__global__ void __launch_bounds__(64) final_kernel(const float* __restrict__ sub,
    const float* __restrict__ hx, const float* __restrict__ u,
    const float* __restrict__ W, const float* __restrict__ b, float* __restrict__ out)
{
    __shared__ float xs[66];
    int i = blockIdx.x, c = threadIdx.x;
    for (int k = c; k < 66; k += 64) xs[k] = sub[i*66+k];
    __syncthreads();
    float a = b[c];
    for (int k = 0; k < 66; k++) a += xs[k]*W[k*64+c];
    float t = tanhf(a);
    float uu = u[i*64+c];
    out[i*64+c] = uu*hx[i*64+c] + (1.f - uu)*t;
}

struct Ptrs {
    float *x,*h,*f1,*f2,*hcat,*sub,*u,*part;
    float2 *pq; float4 *jd; unsigned *mask;
};

static void run_subnet(const Ptrs& P, const float* W, const float* a1, const float* a2,
    const float* Wout, const float* ao1, const float* ao2)
{
    proj_kernel<<<dim3(64,4), 256>>>(P.x, 66, W, a1, a2, P.h, P.f1, P.f2, P.jd);
    rowmax_pq_kernel<4><<<512, 256>>>(P.f1, P.f2, P.mask, P.pq);
    agg_kernel<<<dim3(64,1,4), 256>>>(P.h, P.f1, P.pq, P.jd, P.mask, P.hcat, 264, nullptr);
    proj_kernel<<<dim3(64,1), 256>>>(P.hcat, 264, Wout, ao1, ao2, P.h, P.f1, P.f2, P.jd);
    rowmax_pq_kernel<1><<<512, 256>>>(P.f1, P.f2, P.mask, P.pq);
    agg_kernel<<<dim3(64,4,1), 256>>>(P.h, P.f1, P.pq, P.jd, P.mask, nullptr, 0, P.part);
    reduce_kernel<<<NN, 96>>>(P.part, P.sub);
}

extern "C" void kernel_launch(void* const* d_in, const int* in_sizes, int n_in,
                              void* d_out, int out_size)
{
    const float* inputs = (const float*)d_in[0];
    const float* hx     = (const float*)d_in[1];
    const int*   adj    = (const int*)d_in[2];
    const float* m1_W   = (const float*)d_in[3];
    const float* m1_a1  = (const float*)d_in[4];
    const float* m1_a2  = (const float*)d_in[5];
    const float* m1_Wo  = (const float*)d_in[6];
    const float* m1_ao1 = (const float*)d_in[7];
    const float* m1_ao2 = (const float*)d_in[8];
    const float* m2_W   = (const float*)d_in[9];
    const float* m2_a1  = (const float*)d_in[10];
    const float* m2_a2  = (const float*)d_in[11];
    const float* m2_Wo  = (const float*)d_in[12];
    const float* m2_ao1 = (const float*)d_in[13];
    const float* m2_ao2 = (const float*)d_in[14];
    const float* g1_W   = (const float*)d_in[15];
    const float* g1_b   = (const float*)d_in[16];
    const float* g2_W   = (const float*)d_in[17];
    const float* g2_b   = (const float*)d_in[18];

    Ptrs P; void* t;
    cudaGetSymbolAddress(&t, g_x);    P.x = (float*)t;
    cudaGetSymbolAddress(&t, g_h);    P.h = (float*)t;
    cudaGetSymbolAddress(&t, g_f1);   P.f1 = (float*)t;
    cudaGetSymbolAddress(&t, g_f2);   P.f2 = (float*)t;
    cudaGetSymbolAddress(&t, g_pq);   P.pq = (float2*)t;
    cudaGetSymbolAddress(&t, g_jd);   P.jd = (float4*)t;
    cudaGetSymbolAddress(&t, g_hcat); P.hcat = (float*)t;
    cudaGetSymbolAddress(&t, g_sub);  P.sub = (float*)t;
    cudaGetSymbolAddress(&t, g_u);    P.u = (float*)t;
    cudaGetSymbolAddress(&t, g_part); P.part = (float*)t;
    cudaGetSymbolAddress(&t, g_mask); P.mask = (unsigned*)t;

    pack_mask_kernel<<<2048, 256>>>(adj, P.mask);
    build_x1_kernel<<<(NN*66+255)/256, 256>>>(inputs, hx, P.x);
    run_subnet(P, m1_W, m1_a1, m1_a2, m1_Wo, m1_ao1, m1_ao2);
    gate1_kernel<<<NN, 128>>>(P.sub, hx, g1_W, g1_b, P.x, P.u);
    run_subnet(P, m2_W, m2_a1, m2_a2, m2_Wo, m2_ao1, m2_ao2);
    final_kernel<<<NN, 64>>>(P.sub, hx, P.u, g2_W, g2_b, (float*)d_out);
}

// round 5
// speedup vs baseline: 3.8224x; 3.8224x over previous
#include <cuda_runtime.h>
#include <cstdint>

#define NN 4096
typedef unsigned long long ull;
typedef unsigned int uint32;

__device__ __align__(128) float  g_x[NN*66];
__device__ __align__(128) float  g_h[4*NN*80];
__device__ __align__(128) float  g_f1[4*NN];
__device__ __align__(128) float  g_f2[4*NN];
__device__ __align__(128) float2 g_pq[4*NN];
__device__ __align__(128) float4 g_jd[4*NN];
__device__ __align__(128) float  g_hcat[NN*264];
__device__ __align__(128) float  g_sub[NN*66];
__device__ __align__(128) float  g_u[NN*64];
__device__ __align__(128) float  g_part[4*NN*72];
__device__ __align__(128) unsigned g_mask[NN*128];

__device__ __forceinline__ void cpa16(void* d, const void* s){
    unsigned sd = (unsigned)__cvta_generic_to_shared(d);
    asm volatile("cp.async.ca.shared.global [%0],[%1],16;" :: "r"(sd), "l"(s));
}
#define CP_COMMIT() asm volatile("cp.async.commit_group;")
#define CP_WAIT0()  asm volatile("cp.async.wait_group 0;")

__device__ __forceinline__ uint32 to_tf32(float f){
    uint32 u; asm("cvt.rna.tf32.f32 %0, %1;" : "=r"(u) : "f"(f)); return u;
}
__device__ __forceinline__ void mma_tf32(float4& d, uint32 a0, uint32 a1, uint32 a2, uint32 a3,
                                         uint32 b0, uint32 b1){
    asm("mma.sync.aligned.m16n8k8.row.col.f32.tf32.tf32.f32 "
        "{%0,%1,%2,%3},{%4,%5,%6,%7},{%8,%9},{%0,%1,%2,%3};"
        : "+f"(d.x), "+f"(d.y), "+f"(d.z), "+f"(d.w)
        : "r"(a0), "r"(a1), "r"(a2), "r"(a3), "r"(b0), "r"(b1));
}

__global__ void __launch_bounds__(256) pack_mask_kernel(const int* __restrict__ adj, unsigned* __restrict__ mask){
    int idx = blockIdx.x*256 + threadIdx.x;
    const int4* p = (const int4*)(adj + (size_t)idx*32);
    unsigned m = 0;
#pragma unroll
    for (int q = 0; q < 8; q++){
        int4 v = p[q];
        m |= (v.x>0?1u:0u)<<(q*4+0); m |= (v.y>0?1u:0u)<<(q*4+1);
        m |= (v.z>0?1u:0u)<<(q*4+2); m |= (v.w>0?1u:0u)<<(q*4+3);
    }
    mask[idx] = m;
}

__global__ void __launch_bounds__(256) build_x1_kernel(const float* __restrict__ inputs, const float* __restrict__ hx, float* __restrict__ x){
    int idx = blockIdx.x*256 + threadIdx.x;
    if (idx >= NN*66) return;
    int i = idx/66, c = idx - i*66;
    x[idx] = (c < 2) ? inputs[i*2+c] : hx[i*64 + c-2];
}

// h = x @ W per head (stride-80 out, tf32-rounded, col66=1), + f1/f2/jd epilogue.
template<int ROWS>
__global__ void __launch_bounds__(256) proj_kernel(const float* __restrict__ x, int Din,
    const float* __restrict__ W, const float* __restrict__ a1, const float* __restrict__ a2,
    float* __restrict__ ho, float* __restrict__ f1o, float* __restrict__ f2o, float4* __restrict__ jdo)
{
    constexpr int PR = 256/ROWS;
    __shared__ float Ws[66*66];
    __shared__ float xs[ROWS*67];
    const int head = blockIdx.y;
    const int row0 = blockIdx.x*ROWS;
    const int tid = threadIdx.x;
    W += (size_t)head*Din*66; a1 += head*66; a2 += head*66;
    const int r = tid/PR, part = tid%PR;
    int c0, cnt;
    if (PR == 4){ c0 = (part<2)?part*17:34+(part-2)*16; cnt = (part<2)?17:16; }
    else        { c0 = (part<6)?part*9:54+(part-6)*6;   cnt = (part<6)?9:6; }
    float acc[17];
#pragma unroll
    for (int c = 0; c < 17; c++) acc[c] = 0.f;
    for (int k0 = 0; k0 < Din; k0 += 66){
        __syncthreads();
        for (int idx = tid; idx < 66*66; idx += 256) Ws[idx] = W[(size_t)k0*66 + idx];
        for (int idx = tid; idx < ROWS*66; idx += 256){
            int rr = idx/66, kk = idx - rr*66;
            xs[rr*67+kk] = x[(size_t)(row0+rr)*Din + k0 + kk];
        }
        __syncthreads();
        for (int kk = 0; kk < 66; kk++){
            float xv = xs[r*67+kk];
            const float* wr = Ws + kk*66 + c0;
#pragma unroll
            for (int c = 0; c < 17; c++) if (c < cnt) acc[c] += xv*wr[c];
        }
    }
    float p1 = 0.f, p2 = 0.f;
#pragma unroll
    for (int c = 0; c < 17; c++) if (c < cnt){ p1 += acc[c]*a1[c0+c]; p2 += acc[c]*a2[c0+c]; }
#pragma unroll
    for (int s = 1; s < PR; s <<= 1){
        p1 += __shfl_xor_sync(~0u, p1, s);
        p2 += __shfl_xor_sync(~0u, p2, s);
    }
    int row = row0 + r;
    if (part == 0){
        f1o[head*NN+row] = p1; f2o[head*NN+row] = p2;
        jdo[head*NN+row] = make_float4(p2, __expf(p2), __expf(0.2f*p2), 0.f);
    }
    float* hr = ho + (size_t)(head*NN+row)*80;
#pragma unroll
    for (int c = 0; c < 17; c++) if (c < cnt) hr[c0+c] = __uint_as_float(to_tf32(acc[c]));
    if (part == PR-1){
        hr[66] = 1.0f;
#pragma unroll
        for (int c = 67; c < 80; c++) hr[c] = 0.f;
    }
}

// masked row-max of f2 + P/Q precompute. one block per row, 8 warps split 128 words.
template<int NH>
__global__ void __launch_bounds__(256) rowmax_pq_kernel(const float* __restrict__ f1b,
    const float* __restrict__ f2b, const unsigned* __restrict__ mask, float2* __restrict__ pqo)
{
    __shared__ float red[NH][8];
    const int row = blockIdx.x;
    const int tid = threadIdx.x;
    const int wid = tid>>5, lane = tid&31;
    float m[NH];
#pragma unroll
    for (int h = 0; h < NH; h++) m[h] = -3e38f;
    const unsigned* mrow = mask + (size_t)row*128;
#pragma unroll 4
    for (int k = 0; k < 16; k++){
        unsigned wd = mrow[wid + 8*k];
        bool b = (wd>>lane)&1u;
        int j = (wid + 8*k)*32 + lane;
#pragma unroll
        for (int h = 0; h < NH; h++)
            m[h] = fmaxf(m[h], b ? f2b[h*NN + j] : -3e38f);
    }
#pragma unroll
    for (int h = 0; h < NH; h++){
        float v = m[h];
#pragma unroll
        for (int s = 16; s; s >>= 1) v = fmaxf(v, __shfl_xor_sync(~0u, v, s));
        if (lane == 0) red[h][wid] = v;
    }
    __syncthreads();
    if (tid < NH){
        float v = red[tid][0];
#pragma unroll
        for (int q = 1; q < 8; q++) v = fmaxf(v, red[tid][q]);
        float f1 = f1b[tid*NN + row];
        float e = f1 + v;
        float M = fmaxf(e, 0.2f*e);
        pqo[tid*NN + row] = make_float2(__expf(f1 - M), __expf(0.2f*f1 - M));
    }
}

__device__ __forceinline__ uint32 wcalc(float f1r, float2 pq, float4 jd, unsigned mx, unsigned my, int j){
    float xx = f1r + jd.x;
    float w = (xx > 0.f) ? pq.x*jd.y : pq.y*jd.z;
    unsigned wd = (j & 32) ? my : mx;
    w = ((wd >> (j & 31)) & 1u) ? w : 0.f;
    return to_tf32(w);
}

// tensor-core masked softmax-attention aggregation. 128 rows/block, 256 threads.
__global__ void __launch_bounds__(256) agg_mma_kernel(const float* __restrict__ hb,
    const float* __restrict__ f1b, const float2* __restrict__ pqb, const float4* __restrict__ jdb,
    const unsigned* __restrict__ mask, float* __restrict__ outp, int os, float* __restrict__ partp, int T)
{
    __shared__ float h_B[2][64*76];
    __shared__ float4 jd_s[2][64];
    const int head = blockIdx.z;
    const int row0 = blockIdx.x*128;
    const int tid = threadIdx.x;
    const int wid = tid>>5, lane = tid&31;
    const int g = lane>>2, tig = lane&3;
    const int t0 = blockIdx.y*T;
    const float* hsrc = hb + (size_t)head*NN*80;
    const float4* jds = jdb + head*NN;
    const int r0 = row0 + wid*16 + g;          // this thread's rows: r0, r0+8
    const float f1_0 = f1b[head*NN + r0];
    const float f1_1 = f1b[head*NN + r0 + 8];
    const float2 pq0 = pqb[head*NN + r0];
    const float2 pq1 = pqb[head*NN + r0 + 8];
    const uint2* mrow0 = (const uint2*)(mask + (size_t)r0*128);
    const uint2* mrow1 = (const uint2*)(mask + (size_t)(r0+8)*128);

    float4 acc[9];
#pragma unroll
    for (int nt = 0; nt < 9; nt++) acc[nt] = make_float4(0.f,0.f,0.f,0.f);

    // prefetch chunk t0
#pragma unroll
    for (int i = 0; i < 5; i++){
        int idx = tid + i*256;
        if (idx < 1152){
            int jr = idx/18, c4 = idx - jr*18;
            cpa16(&h_B[0][jr*76 + c4*4], hsrc + (size_t)(t0*64 + jr)*80 + c4*4);
        }
    }
    if (tid < 64) cpa16(&jd_s[0][tid], &jds[t0*64 + tid]);
    CP_COMMIT();
    uint2 m0 = mrow0[t0], m1 = mrow1[t0];
    CP_WAIT0();
    __syncthreads();

    int buf = 0;
    for (int tt = 0; tt < T; tt++){
        const int t = t0 + tt;
        const bool more = (tt + 1 < T);
        if (more){
#pragma unroll
            for (int i = 0; i < 5; i++){
                int idx = tid + i*256;
                if (idx < 1152){
                    int jr = idx/18, c4 = idx - jr*18;
                    cpa16(&h_B[buf^1][jr*76 + c4*4], hsrc + (size_t)((t+1)*64 + jr)*80 + c4*4);
                }
            }
            if (tid < 64) cpa16(&jd_s[buf^1][tid], &jds[(t+1)*64 + tid]);
            CP_COMMIT();
        }
        uint2 nm0 = make_uint2(0,0), nm1 = make_uint2(0,0);
        if (more){ nm0 = mrow0[t+1]; nm1 = mrow1[t+1]; }

#pragma unroll
        for (int ks = 0; ks < 8; ks++){
            const int j0 = ks*8 + tig, j1 = j0 + 4;
            float4 jd0 = jd_s[buf][j0];
            float4 jd1 = jd_s[buf][j1];
            uint32 a0 = wcalc(f1_0, pq0, jd0, m0.x, m0.y, j0);
            uint32 a1 = wcalc(f1_1, pq1, jd0, m1.x, m1.y, j0);
            uint32 a2 = wcalc(f1_0, pq0, jd1, m0.x, m0.y, j1);
            uint32 a3 = wcalc(f1_1, pq1, jd1, m1.x, m1.y, j1);
            const float* hb0 = &h_B[buf][(ks*8 + tig)*76];
            const float* hb1 = hb0 + 4*76;
#pragma unroll
            for (int nt = 0; nt < 9; nt++){
                uint32 b0 = __float_as_uint(hb0[nt*8 + g]);
                uint32 b1 = __float_as_uint(hb1[nt*8 + g]);
                mma_tf32(acc[nt], a0, a1, a2, a3, b0, b1);
            }
        }
        if (more) CP_WAIT0();
        __syncthreads();
        buf ^= 1; m0 = nm0; m1 = nm1;
    }

    if (partp){
        float* p0 = partp + ((size_t)blockIdx.y*NN + r0)*72;
        float* p1 = p0 + 8*72;
#pragma unroll
        for (int nt = 0; nt < 9; nt++){
            int c = nt*8 + 2*tig;
            if (c < 66){
                p0[c] = acc[nt].x; p1[c] = acc[nt].z;
                if (c + 1 < 66){ p0[c+1] = acc[nt].y; p1[c+1] = acc[nt].w; }
            }
        }
        if (tig == 1){ p0[66] = acc[8].x; p1[66] = acc[8].z; }
    } else {
        float den0 = __shfl_sync(~0u, acc[8].x, (lane & ~3) | 1);
        float den1 = __shfl_sync(~0u, acc[8].z, (lane & ~3) | 1);
        float inv0 = 1.f/den0, inv1 = 1.f/den1;
        float* o0 = outp + (size_t)r0*os + head*66;
        float* o1 = o0 + 8*os;
#pragma unroll
        for (int nt = 0; nt < 9; nt++){
            int c = nt*8 + 2*tig;
            if (c < 66){
                float v;
                v = acc[nt].x*inv0; o0[c] = fmaxf(v, 0.01f*v);
                v = acc[nt].z*inv1; o1[c] = fmaxf(v, 0.01f*v);
                if (c + 1 < 66){
                    v = acc[nt].y*inv0; o0[c+1] = fmaxf(v, 0.01f*v);
                    v = acc[nt].w*inv1; o1[c+1] = fmaxf(v, 0.01f*v);
                }
            }
        }
    }
}

__global__ void __launch_bounds__(96) reduce_kernel(const float* __restrict__ part, float* __restrict__ out){
    int i = blockIdx.x, c = threadIdx.x;
    if (c >= 66) return;
    float num = 0.f, den = 0.f;
#pragma unroll
    for (int k = 0; k < 4; k++){
        const float* p = part + ((size_t)k*NN + i)*72;
        num += p[c]; den += p[66];
    }
    float v = num/den;
    out[i*66 + c] = fmaxf(v, 0.01f*v);
}

__global__ void __launch_bounds__(128) gate1_kernel(const float* __restrict__ sub,
    const float* __restrict__ hx, const float* __restrict__ W, const float* __restrict__ b,
    float* __restrict__ xout, float* __restrict__ uout)
{
    __shared__ float xs[66];
    int i = blockIdx.x, c = threadIdx.x;
    for (int k = c; k < 66; k += 128) xs[k] = sub[i*66+k];
    __syncthreads();
    float a = b[c];
    for (int k = 0; k < 66; k++) a += xs[k]*W[k*128+c];
    float v = 1.f/(1.f + __expf(-a));
    if (c < 64) xout[i*66 + 2 + c] = v*hx[i*64+c];
    else uout[i*64 + c - 64] = v;
}

__global__ void __launch_bounds__(64) final_kernel(const float* __restrict__ sub,
    const float* __restrict__ hx, const float* __restrict__ u,
    const float* __restrict__ W, const float* __restrict__ b, float* __restrict__ out)
{
    __shared__ float xs[66];
    int i = blockIdx.x, c = threadIdx.x;
    for (int k = c; k < 66; k += 64) xs[k] = sub[i*66+k];
    __syncthreads();
    float a = b[c];
    for (int k = 0; k < 66; k++) a += xs[k]*W[k*64+c];
    float t = tanhf(a);
    float uu = u[i*64+c];
    out[i*64+c] = uu*hx[i*64+c] + (1.f - uu)*t;
}

struct Ptrs {
    float *x,*h,*f1,*f2,*hcat,*sub,*u,*part;
    float2 *pq; float4 *jd; unsigned *mask;
};

static void run_subnet(const Ptrs& P, const float* W, const float* a1, const float* a2,
    const float* Wout, const float* ao1, const float* ao2)
{
    proj_kernel<64><<<dim3(64,4), 256>>>(P.x, 66, W, a1, a2, P.h, P.f1, P.f2, P.jd);
    rowmax_pq_kernel<4><<<NN, 256>>>(P.f1, P.f2, P.mask, P.pq);
    agg_mma_kernel<<<dim3(32,1,4), 256>>>(P.h, P.f1, P.pq, P.jd, P.mask, P.hcat, 264, nullptr, 64);
    proj_kernel<32><<<dim3(128,1), 256>>>(P.hcat, 264, Wout, ao1, ao2, P.h, P.f1, P.f2, P.jd);
    rowmax_pq_kernel<1><<<NN, 256>>>(P.f1, P.f2, P.mask, P.pq);
    agg_mma_kernel<<<dim3(32,4,1), 256>>>(P.h, P.f1, P.pq, P.jd, P.mask, nullptr, 0, P.part, 16);
    reduce_kernel<<<NN, 96>>>(P.part, P.sub);
}

extern "C" void kernel_launch(void* const* d_in, const int* in_sizes, int n_in,
                              void* d_out, int out_size)
{
    const float* inputs = (const float*)d_in[0];
    const float* hx     = (const float*)d_in[1];
    const int*   adj    = (const int*)d_in[2];
    const float* m1_W   = (const float*)d_in[3];
    const float* m1_a1  = (const float*)d_in[4];
    const float* m1_a2  = (const float*)d_in[5];
    const float* m1_Wo  = (const float*)d_in[6];
    const float* m1_ao1 = (const float*)d_in[7];
    const float* m1_ao2 = (const float*)d_in[8];
    const float* m2_W   = (const float*)d_in[9];
    const float* m2_a1  = (const float*)d_in[10];
    const float* m2_a2  = (const float*)d_in[11];
    const float* m2_Wo  = (const float*)d_in[12];
    const float* m2_ao1 = (const float*)d_in[13];
    const float* m2_ao2 = (const float*)d_in[14];
    const float* g1_W   = (const float*)d_in[15];
    const float* g1_b   = (const float*)d_in[16];
    const float* g2_W   = (const float*)d_in[17];
    const float* g2_b   = (const float*)d_in[18];

    Ptrs P; void* t;
    cudaGetSymbolAddress(&t, g_x);    P.x = (float*)t;
    cudaGetSymbolAddress(&t, g_h);    P.h = (float*)t;
    cudaGetSymbolAddress(&t, g_f1);   P.f1 = (float*)t;
    cudaGetSymbolAddress(&t, g_f2);   P.f2 = (float*)t;
    cudaGetSymbolAddress(&t, g_pq);   P.pq = (float2*)t;
    cudaGetSymbolAddress(&t, g_jd);   P.jd = (float4*)t;
    cudaGetSymbolAddress(&t, g_hcat); P.hcat = (float*)t;
    cudaGetSymbolAddress(&t, g_sub);  P.sub = (float*)t;
    cudaGetSymbolAddress(&t, g_u);    P.u = (float*)t;
    cudaGetSymbolAddress(&t, g_part); P.part = (float*)t;
    cudaGetSymbolAddress(&t, g_mask); P.mask = (unsigned*)t;

    pack_mask_kernel<<<2048, 256>>>(adj, P.mask);
    build_x1_kernel<<<(NN*66+255)/256, 256>>>(inputs, hx, P.x);
    run_subnet(P, m1_W, m1_a1, m1_a2, m1_Wo, m1_ao1, m1_ao2);
    gate1_kernel<<<NN, 128>>>(P.sub, hx, g1_W, g1_b, P.x, P.u);
    run_subnet(P, m2_W, m2_a1, m2_a2, m2_Wo, m2_ao1, m2_ao2);
    final_kernel<<<NN, 64>>>(P.sub, hx, P.u, g2_W, g2_b, (float*)d_out);
}

// round 6
// speedup vs baseline: 4.2206x; 1.1042x over previous
#include <cuda_runtime.h>
#include <cstdint>

#define NN 4096
typedef unsigned long long ull;
typedef unsigned int uint32;

__device__ __align__(128) float  g_x[NN*66];
__device__ __align__(128) float  g_h[4*NN*80];
__device__ __align__(128) float  g_f1[4*NN];
__device__ __align__(128) float2 g_pq[4*NN];
__device__ __align__(128) float4 g_jd[4*NN];
__device__ __align__(128) float  g_hcat[NN*264];
__device__ __align__(128) float  g_sub[NN*66];
__device__ __align__(128) float  g_u[NN*64];
__device__ __align__(128) float  g_part[4*NN*72];
__device__ __align__(128) unsigned g_mask[NN*128];

__device__ __forceinline__ void cpa16(void* d, const void* s){
    unsigned sd = (unsigned)__cvta_generic_to_shared(d);
    asm volatile("cp.async.ca.shared.global [%0],[%1],16;" :: "r"(sd), "l"(s));
}
#define CP_COMMIT() asm volatile("cp.async.commit_group;")
#define CP_WAIT0()  asm volatile("cp.async.wait_group 0;")

__device__ __forceinline__ uint32 to_tf32(float f){
    uint32 u; asm("cvt.rna.tf32.f32 %0, %1;" : "=r"(u) : "f"(f)); return u;
}
__device__ __forceinline__ void mma_tf32(float4& d, uint32 a0, uint32 a1, uint32 a2, uint32 a3,
                                         uint32 b0, uint32 b1){
    asm("mma.sync.aligned.m16n8k8.row.col.f32.tf32.tf32.f32 "
        "{%0,%1,%2,%3},{%4,%5,%6,%7},{%8,%9},{%0,%1,%2,%3};"
        : "+f"(d.x), "+f"(d.y), "+f"(d.z), "+f"(d.w)
        : "r"(a0), "r"(a1), "r"(a2), "r"(a3), "r"(b0), "r"(b1));
}

__global__ void __launch_bounds__(256) pack_mask_kernel(const int* __restrict__ adj, unsigned* __restrict__ mask){
    int idx = blockIdx.x*256 + threadIdx.x;
    const int4* p = (const int4*)(adj + (size_t)idx*32);
    unsigned m = 0;
#pragma unroll
    for (int q = 0; q < 8; q++){
        int4 v = p[q];
        m |= (v.x>0?1u:0u)<<(q*4+0); m |= (v.y>0?1u:0u)<<(q*4+1);
        m |= (v.z>0?1u:0u)<<(q*4+2); m |= (v.w>0?1u:0u)<<(q*4+3);
    }
    mask[idx] = m;
}

__global__ void __launch_bounds__(256) build_x1_kernel(const float* __restrict__ inputs, const float* __restrict__ hx, float* __restrict__ x){
    int idx = blockIdx.x*256 + threadIdx.x;
    if (idx >= NN*66) return;
    int i = idx/66, c = idx - i*66;
    x[idx] = (c < 2) ? inputs[i*2+c] : hx[i*64 + c-2];
}

// h = x @ W per head (stride-80 out, tf32-rounded, col66=1) + f1/jd/pq epilogue.
// No softmax max-subtraction needed: e in [-~10,~10], exp safe in fp32.
template<int ROWS>
__global__ void __launch_bounds__(256) proj_kernel(const float* __restrict__ x, int Din,
    const float* __restrict__ W, const float* __restrict__ a1, const float* __restrict__ a2,
    float* __restrict__ ho, float* __restrict__ f1o, float2* __restrict__ pqo, float4* __restrict__ jdo)
{
    constexpr int PR = 256/ROWS;
    __shared__ float Ws[66*66];
    __shared__ float xs[ROWS*67];
    const int head = blockIdx.y;
    const int row0 = blockIdx.x*ROWS;
    const int tid = threadIdx.x;
    W += (size_t)head*Din*66; a1 += head*66; a2 += head*66;
    const int r = tid/PR, part = tid%PR;
    int c0, cnt;
    if (PR == 4){ c0 = (part<2)?part*17:34+(part-2)*16; cnt = (part<2)?17:16; }
    else        { c0 = (part<6)?part*9:54+(part-6)*6;   cnt = (part<6)?9:6; }
    float acc[17];
#pragma unroll
    for (int c = 0; c < 17; c++) acc[c] = 0.f;
    for (int k0 = 0; k0 < Din; k0 += 66){
        __syncthreads();
        for (int idx = tid; idx < 66*66; idx += 256) Ws[idx] = W[(size_t)k0*66 + idx];
        for (int idx = tid; idx < ROWS*66; idx += 256){
            int rr = idx/66, kk = idx - rr*66;
            xs[rr*67+kk] = x[(size_t)(row0+rr)*Din + k0 + kk];
        }
        __syncthreads();
        for (int kk = 0; kk < 66; kk++){
            float xv = xs[r*67+kk];
            const float* wr = Ws + kk*66 + c0;
#pragma unroll
            for (int c = 0; c < 17; c++) if (c < cnt) acc[c] += xv*wr[c];
        }
    }
    float p1 = 0.f, p2 = 0.f;
#pragma unroll
    for (int c = 0; c < 17; c++) if (c < cnt){ p1 += acc[c]*a1[c0+c]; p2 += acc[c]*a2[c0+c]; }
#pragma unroll
    for (int s = 1; s < PR; s <<= 1){
        p1 += __shfl_xor_sync(~0u, p1, s);
        p2 += __shfl_xor_sync(~0u, p2, s);
    }
    int row = row0 + r;
    if (part == 0){
        f1o[head*NN+row] = p1;
        pqo[head*NN+row] = make_float2(__expf(p1), __expf(0.2f*p1));
        jdo[head*NN+row] = make_float4(p2, __expf(p2), __expf(0.2f*p2), 0.f);
    }
    float* hr = ho + (size_t)(head*NN+row)*80;
#pragma unroll
    for (int c = 0; c < 17; c++) if (c < cnt) hr[c0+c] = __uint_as_float(to_tf32(acc[c]));
    if (part == PR-1){
        hr[66] = 1.0f;
#pragma unroll
        for (int c = 67; c < 80; c++) hr[c] = 0.f;
    }
}

__device__ __forceinline__ uint32 wcalc(float f1r, float2 pq, float4 jd, unsigned mx, unsigned my, int j){
    float xx = f1r + jd.x;
    float w = (xx > 0.f) ? pq.x*jd.y : pq.y*jd.z;
    unsigned wd = (j & 32) ? my : mx;
    w = ((wd >> (j & 31)) & 1u) ? w : 0.f;
    return to_tf32(w);
}

// tensor-core masked softmax-attention aggregation. 128 rows/block, 256 threads.
__global__ void __launch_bounds__(256) agg_mma_kernel(const float* __restrict__ hb,
    const float* __restrict__ f1b, const float2* __restrict__ pqb, const float4* __restrict__ jdb,
    const unsigned* __restrict__ mask, float* __restrict__ outp, int os, float* __restrict__ partp, int T)
{
    __shared__ float h_B[2][64*76];
    __shared__ float4 jd_s[2][64];
    const int head = blockIdx.z;
    const int row0 = blockIdx.x*128;
    const int tid = threadIdx.x;
    const int wid = tid>>5, lane = tid&31;
    const int g = lane>>2, tig = lane&3;
    const int t0 = blockIdx.y*T;
    const float* hsrc = hb + (size_t)head*NN*80;
    const float4* jds = jdb + head*NN;
    const int r0 = row0 + wid*16 + g;          // this thread's rows: r0, r0+8
    const float f1_0 = f1b[head*NN + r0];
    const float f1_1 = f1b[head*NN + r0 + 8];
    const float2 pq0 = pqb[head*NN + r0];
    const float2 pq1 = pqb[head*NN + r0 + 8];
    const uint2* mrow0 = (const uint2*)(mask + (size_t)r0*128);
    const uint2* mrow1 = (const uint2*)(mask + (size_t)(r0+8)*128);

    float4 acc[9];
#pragma unroll
    for (int nt = 0; nt < 9; nt++) acc[nt] = make_float4(0.f,0.f,0.f,0.f);

    // prefetch chunk t0
#pragma unroll
    for (int i = 0; i < 5; i++){
        int idx = tid + i*256;
        if (idx < 1152){
            int jr = idx/18, c4 = idx - jr*18;
            cpa16(&h_B[0][jr*76 + c4*4], hsrc + (size_t)(t0*64 + jr)*80 + c4*4);
        }
    }
    if (tid < 64) cpa16(&jd_s[0][tid], &jds[t0*64 + tid]);
    CP_COMMIT();
    uint2 m0 = mrow0[t0], m1 = mrow1[t0];
    CP_WAIT0();
    __syncthreads();

    int buf = 0;
    for (int tt = 0; tt < T; tt++){
        const int t = t0 + tt;
        const bool more = (tt + 1 < T);
        if (more){
#pragma unroll
            for (int i = 0; i < 5; i++){
                int idx = tid + i*256;
                if (idx < 1152){
                    int jr = idx/18, c4 = idx - jr*18;
                    cpa16(&h_B[buf^1][jr*76 + c4*4], hsrc + (size_t)((t+1)*64 + jr)*80 + c4*4);
                }
            }
            if (tid < 64) cpa16(&jd_s[buf^1][tid], &jds[(t+1)*64 + tid]);
            CP_COMMIT();
        }
        uint2 nm0 = make_uint2(0,0), nm1 = make_uint2(0,0);
        if (more){ nm0 = mrow0[t+1]; nm1 = mrow1[t+1]; }

#pragma unroll
        for (int ks = 0; ks < 8; ks++){
            const int j0 = ks*8 + tig, j1 = j0 + 4;
            float4 jd0 = jd_s[buf][j0];
            float4 jd1 = jd_s[buf][j1];
            uint32 a0 = wcalc(f1_0, pq0, jd0, m0.x, m0.y, j0);
            uint32 a1 = wcalc(f1_1, pq1, jd0, m1.x, m1.y, j0);
            uint32 a2 = wcalc(f1_0, pq0, jd1, m0.x, m0.y, j1);
            uint32 a3 = wcalc(f1_1, pq1, jd1, m1.x, m1.y, j1);
            const float* hb0 = &h_B[buf][(ks*8 + tig)*76];
            const float* hb1 = hb0 + 4*76;
#pragma unroll
            for (int nt = 0; nt < 9; nt++){
                uint32 b0 = __float_as_uint(hb0[nt*8 + g]);
                uint32 b1 = __float_as_uint(hb1[nt*8 + g]);
                mma_tf32(acc[nt], a0, a1, a2, a3, b0, b1);
            }
        }
        if (more) CP_WAIT0();
        __syncthreads();
        buf ^= 1; m0 = nm0; m1 = nm1;
    }

    if (partp){
        float* p0 = partp + ((size_t)blockIdx.y*NN + r0)*72;
        float* p1 = p0 + 8*72;
#pragma unroll
        for (int nt = 0; nt < 9; nt++){
            int c = nt*8 + 2*tig;
            if (c < 66){
                p0[c] = acc[nt].x; p1[c] = acc[nt].z;
                if (c + 1 < 66){ p0[c+1] = acc[nt].y; p1[c+1] = acc[nt].w; }
            }
        }
        if (tig == 1){ p0[66] = acc[8].x; p1[66] = acc[8].z; }
    } else {
        float den0 = __shfl_sync(~0u, acc[8].x, (lane & ~3) | 1);
        float den1 = __shfl_sync(~0u, acc[8].z, (lane & ~3) | 1);
        float inv0 = 1.f/den0, inv1 = 1.f/den1;
        float* o0 = outp + (size_t)r0*os + head*66;
        float* o1 = o0 + 8*os;
#pragma unroll
        for (int nt = 0; nt < 9; nt++){
            int c = nt*8 + 2*tig;
            if (c < 66){
                float v;
                v = acc[nt].x*inv0; o0[c] = fmaxf(v, 0.01f*v);
                v = acc[nt].z*inv1; o1[c] = fmaxf(v, 0.01f*v);
                if (c + 1 < 66){
                    v = acc[nt].y*inv0; o0[c+1] = fmaxf(v, 0.01f*v);
                    v = acc[nt].w*inv1; o1[c+1] = fmaxf(v, 0.01f*v);
                }
            }
        }
    }
}

__global__ void __launch_bounds__(96) reduce_kernel(const float* __restrict__ part, float* __restrict__ out){
    int i = blockIdx.x, c = threadIdx.x;
    if (c >= 66) return;
    float num = 0.f, den = 0.f;
#pragma unroll
    for (int k = 0; k < 4; k++){
        const float* p = part + ((size_t)k*NN + i)*72;
        num += p[c]; den += p[66];
    }
    float v = num/den;
    out[i*66 + c] = fmaxf(v, 0.01f*v);
}

__global__ void __launch_bounds__(128) gate1_kernel(const float* __restrict__ sub,
    const float* __restrict__ hx, const float* __restrict__ W, const float* __restrict__ b,
    float* __restrict__ xout, float* __restrict__ uout)
{
    __shared__ float xs[66];
    int i = blockIdx.x, c = threadIdx.x;
    for (int k = c; k < 66; k += 128) xs[k] = sub[i*66+k];
    __syncthreads();
    float a = b[c];
    for (int k = 0; k < 66; k++) a += xs[k]*W[k*128+c];
    float v = 1.f/(1.f + __expf(-a));
    if (c < 64) xout[i*66 + 2 + c] = v*hx[i*64+c];
    else uout[i*64 + c - 64] = v;
}

__global__ void __launch_bounds__(64) final_kernel(const float* __restrict__ sub,
    const float* __restrict__ hx, const float* __restrict__ u,
    const float* __restrict__ W, const float* __restrict__ b, float* __restrict__ out)
{
    __shared__ float xs[66];
    int i = blockIdx.x, c = threadIdx.x;
    for (int k = c; k < 66; k += 64) xs[k] = sub[i*66+k];
    __syncthreads();
    float a = b[c];
    for (int k = 0; k < 66; k++) a += xs[k]*W[k*64+c];
    float t = tanhf(a);
    float uu = u[i*64+c];
    out[i*64+c] = uu*hx[i*64+c] + (1.f - uu)*t;
}

struct Ptrs {
    float *x,*h,*f1,*hcat,*sub,*u,*part;
    float2 *pq; float4 *jd; unsigned *mask;
};

static void run_subnet(const Ptrs& P, const float* W, const float* a1, const float* a2,
    const float* Wout, const float* ao1, const float* ao2)
{
    proj_kernel<64><<<dim3(64,4), 256>>>(P.x, 66, W, a1, a2, P.h, P.f1, P.pq, P.jd);
    agg_mma_kernel<<<dim3(32,1,4), 256>>>(P.h, P.f1, P.pq, P.jd, P.mask, P.hcat, 264, nullptr, 64);
    proj_kernel<32><<<dim3(128,1), 256>>>(P.hcat, 264, Wout, ao1, ao2, P.h, P.f1, P.pq, P.jd);
    agg_mma_kernel<<<dim3(32,4,1), 256>>>(P.h, P.f1, P.pq, P.jd, P.mask, nullptr, 0, P.part, 16);
    reduce_kernel<<<NN, 96>>>(P.part, P.sub);
}

extern "C" void kernel_launch(void* const* d_in, const int* in_sizes, int n_in,
                              void* d_out, int out_size)
{
    const float* inputs = (const float*)d_in[0];
    const float* hx     = (const float*)d_in[1];
    const int*   adj    = (const int*)d_in[2];
    const float* m1_W   = (const float*)d_in[3];
    const float* m1_a1  = (const float*)d_in[4];
    const float* m1_a2  = (const float*)d_in[5];
    const float* m1_Wo  = (const float*)d_in[6];
    const float* m1_ao1 = (const float*)d_in[7];
    const float* m1_ao2 = (const float*)d_in[8];
    const float* m2_W   = (const float*)d_in[9];
    const float* m2_a1  = (const float*)d_in[10];
    const float* m2_a2  = (const float*)d_in[11];
    const float* m2_Wo  = (const float*)d_in[12];
    const float* m2_ao1 = (const float*)d_in[13];
    const float* m2_ao2 = (const float*)d_in[14];
    const float* g1_W   = (const float*)d_in[15];
    const float* g1_b   = (const float*)d_in[16];
    const float* g2_W   = (const float*)d_in[17];
    const float* g2_b   = (const float*)d_in[18];

    Ptrs P; void* t;
    cudaGetSymbolAddress(&t, g_x);    P.x = (float*)t;
    cudaGetSymbolAddress(&t, g_h);    P.h = (float*)t;
    cudaGetSymbolAddress(&t, g_f1);   P.f1 = (float*)t;
    cudaGetSymbolAddress(&t, g_pq);   P.pq = (float2*)t;
    cudaGetSymbolAddress(&t, g_jd);   P.jd = (float4*)t;
    cudaGetSymbolAddress(&t, g_hcat); P.hcat = (float*)t;
    cudaGetSymbolAddress(&t, g_sub);  P.sub = (float*)t;
    cudaGetSymbolAddress(&t, g_u);    P.u = (float*)t;
    cudaGetSymbolAddress(&t, g_part); P.part = (float*)t;
    cudaGetSymbolAddress(&t, g_mask); P.mask = (unsigned*)t;

    pack_mask_kernel<<<2048, 256>>>(adj, P.mask);
    build_x1_kernel<<<(NN*66+255)/256, 256>>>(inputs, hx, P.x);
    run_subnet(P, m1_W, m1_a1, m1_a2, m1_Wo, m1_ao1, m1_ao2);
    gate1_kernel<<<NN, 128>>>(P.sub, hx, g1_W, g1_b, P.x, P.u);
    run_subnet(P, m2_W, m2_a1, m2_a2, m2_Wo, m2_ao1, m2_ao2);
    final_kernel<<<NN, 64>>>(P.sub, hx, P.u, g2_W, g2_b, (float*)d_out);
}

// round 7
// speedup vs baseline: 4.2635x; 1.0102x over previous
#include <cuda_runtime.h>
#include <cstdint>

#define NN 4096
typedef unsigned long long ull;
typedef unsigned int uint32;

__device__ __align__(128) float  g_x[NN*66];
__device__ __align__(128) float  g_h[4*NN*80];
__device__ __align__(128) float  g_f1[4*NN];
__device__ __align__(128) float2 g_pq[4*NN];
__device__ __align__(128) float4 g_jd[4*NN];
__device__ __align__(128) float  g_hcat[NN*264];
__device__ __align__(128) float  g_sub[NN*66];
__device__ __align__(128) float  g_u[NN*64];
__device__ __align__(128) float  g_part[8UL*NN*72];
__device__ __align__(128) unsigned g_mask[NN*128];

__device__ __forceinline__ void cpa16(void* d, const void* s){
    unsigned sd = (unsigned)__cvta_generic_to_shared(d);
    asm volatile("cp.async.ca.shared.global [%0],[%1],16;" :: "r"(sd), "l"(s));
}
#define CP_COMMIT() asm volatile("cp.async.commit_group;")
#define CP_WAIT0()  asm volatile("cp.async.wait_group 0;")

__device__ __forceinline__ uint32 to_tf32(float f){
    uint32 u; asm("cvt.rna.tf32.f32 %0, %1;" : "=r"(u) : "f"(f)); return u;
}
__device__ __forceinline__ void mma_tf32(float4& d, uint32 a0, uint32 a1, uint32 a2, uint32 a3,
                                         uint32 b0, uint32 b1){
    asm("mma.sync.aligned.m16n8k8.row.col.f32.tf32.tf32.f32 "
        "{%0,%1,%2,%3},{%4,%5,%6,%7},{%8,%9},{%0,%1,%2,%3};"
        : "+f"(d.x), "+f"(d.y), "+f"(d.z), "+f"(d.w)
        : "r"(a0), "r"(a1), "r"(a2), "r"(a3), "r"(b0), "r"(b1));
}

__global__ void __launch_bounds__(256) pack_mask_kernel(const int* __restrict__ adj, unsigned* __restrict__ mask){
    int idx = blockIdx.x*256 + threadIdx.x;
    const int4* p = (const int4*)(adj + (size_t)idx*32);
    unsigned m = 0;
#pragma unroll
    for (int q = 0; q < 8; q++){
        int4 v = p[q];
        m |= (v.x>0?1u:0u)<<(q*4+0); m |= (v.y>0?1u:0u)<<(q*4+1);
        m |= (v.z>0?1u:0u)<<(q*4+2); m |= (v.w>0?1u:0u)<<(q*4+3);
    }
    mask[idx] = m;
}

__global__ void __launch_bounds__(256) build_x1_kernel(const float* __restrict__ inputs, const float* __restrict__ hx, float* __restrict__ x){
    int idx = blockIdx.x*256 + threadIdx.x;
    if (idx >= NN*66) return;
    int i = idx/66, c = idx - i*66;
    x[idx] = (c < 2) ? inputs[i*2+c] : hx[i*64 + c-2];
}

// h = x @ W per head (stride-80 out, tf32-rounded, col66=1) + f1/jd/pq epilogue.
template<int ROWS>
__global__ void __launch_bounds__(256) proj_kernel(const float* __restrict__ x, int Din,
    const float* __restrict__ W, const float* __restrict__ a1, const float* __restrict__ a2,
    float* __restrict__ ho, float* __restrict__ f1o, float2* __restrict__ pqo, float4* __restrict__ jdo)
{
    constexpr int PR = 256/ROWS;
    __shared__ float Ws[66*66];
    __shared__ float xs[ROWS*67];
    const int head = blockIdx.y;
    const int row0 = blockIdx.x*ROWS;
    const int tid = threadIdx.x;
    W += (size_t)head*Din*66; a1 += head*66; a2 += head*66;
    const int r = tid/PR, part = tid%PR;
    int c0, cnt;
    if (PR == 4){ c0 = (part<2)?part*17:34+(part-2)*16; cnt = (part<2)?17:16; }
    else        { c0 = (part<6)?part*9:54+(part-6)*6;   cnt = (part<6)?9:6; }
    float acc[17];
#pragma unroll
    for (int c = 0; c < 17; c++) acc[c] = 0.f;
    for (int k0 = 0; k0 < Din; k0 += 66){
        __syncthreads();
        for (int idx = tid; idx < 66*66; idx += 256) Ws[idx] = W[(size_t)k0*66 + idx];
        for (int idx = tid; idx < ROWS*66; idx += 256){
            int rr = idx/66, kk = idx - rr*66;
            xs[rr*67+kk] = x[(size_t)(row0+rr)*Din + k0 + kk];
        }
        __syncthreads();
        for (int kk = 0; kk < 66; kk++){
            float xv = xs[r*67+kk];
            const float* wr = Ws + kk*66 + c0;
#pragma unroll
            for (int c = 0; c < 17; c++) if (c < cnt) acc[c] += xv*wr[c];
        }
    }
    float p1 = 0.f, p2 = 0.f;
#pragma unroll
    for (int c = 0; c < 17; c++) if (c < cnt){ p1 += acc[c]*a1[c0+c]; p2 += acc[c]*a2[c0+c]; }
#pragma unroll
    for (int s = 1; s < PR; s <<= 1){
        p1 += __shfl_xor_sync(~0u, p1, s);
        p2 += __shfl_xor_sync(~0u, p2, s);
    }
    int row = row0 + r;
    if (part == 0){
        f1o[head*NN+row] = p1;
        pqo[head*NN+row] = make_float2(__expf(p1), __expf(0.2f*p1));
        jdo[head*NN+row] = make_float4(p2, __expf(p2), __expf(0.2f*p2), 0.f);
    }
    float* hr = ho + (size_t)(head*NN+row)*80;
#pragma unroll
    for (int c = 0; c < 17; c++) if (c < cnt) hr[c0+c] = __uint_as_float(to_tf32(acc[c]));
    if (part == PR-1){
        hr[66] = 1.0f;
#pragma unroll
        for (int c = 67; c < 80; c++) hr[c] = 0.f;
    }
}

__device__ __forceinline__ uint32 wcalc(float f1r, float2 pq, float4 jd, unsigned mx, unsigned my, int j){
    float xx = f1r + jd.x;
    float w = (xx > 0.f) ? pq.x*jd.y : pq.y*jd.z;
    unsigned wd = (j & 32) ? my : mx;
    w = ((wd >> (j & 31)) & 1u) ? w : 0.f;
    return to_tf32(w);
}

// tensor-core masked softmax-attention aggregation. 128 rows/block, 256 threads.
// Always writes partial (num, den) to g_part slot (head*gridDim.y + blockIdx.y).
__global__ void __launch_bounds__(256) agg_mma_kernel(const float* __restrict__ hb,
    const float* __restrict__ f1b, const float2* __restrict__ pqb, const float4* __restrict__ jdb,
    const unsigned* __restrict__ mask, float* __restrict__ partp, int T)
{
    __shared__ float h_B[2][64*76];
    __shared__ float4 jd_s[2][64];
    const int head = blockIdx.z;
    const int row0 = blockIdx.x*128;
    const int tid = threadIdx.x;
    const int wid = tid>>5, lane = tid&31;
    const int g = lane>>2, tig = lane&3;
    const int t0 = blockIdx.y*T;
    const float* hsrc = hb + (size_t)head*NN*80;
    const float4* jds = jdb + head*NN;
    const int r0 = row0 + wid*16 + g;          // this thread's rows: r0, r0+8
    const float f1_0 = f1b[head*NN + r0];
    const float f1_1 = f1b[head*NN + r0 + 8];
    const float2 pq0 = pqb[head*NN + r0];
    const float2 pq1 = pqb[head*NN + r0 + 8];
    const uint2* mrow0 = (const uint2*)(mask + (size_t)r0*128);
    const uint2* mrow1 = (const uint2*)(mask + (size_t)(r0+8)*128);

    float4 acc[9];
#pragma unroll
    for (int nt = 0; nt < 9; nt++) acc[nt] = make_float4(0.f,0.f,0.f,0.f);

    // prefetch chunk t0
#pragma unroll
    for (int i = 0; i < 5; i++){
        int idx = tid + i*256;
        if (idx < 1152){
            int jr = idx/18, c4 = idx - jr*18;
            cpa16(&h_B[0][jr*76 + c4*4], hsrc + (size_t)(t0*64 + jr)*80 + c4*4);
        }
    }
    if (tid < 64) cpa16(&jd_s[0][tid], &jds[t0*64 + tid]);
    CP_COMMIT();
    uint2 m0 = mrow0[t0], m1 = mrow1[t0];
    CP_WAIT0();
    __syncthreads();

    int buf = 0;
    for (int tt = 0; tt < T; tt++){
        const int t = t0 + tt;
        const bool more = (tt + 1 < T);
        if (more){
#pragma unroll
            for (int i = 0; i < 5; i++){
                int idx = tid + i*256;
                if (idx < 1152){
                    int jr = idx/18, c4 = idx - jr*18;
                    cpa16(&h_B[buf^1][jr*76 + c4*4], hsrc + (size_t)((t+1)*64 + jr)*80 + c4*4);
                }
            }
            if (tid < 64) cpa16(&jd_s[buf^1][tid], &jds[(t+1)*64 + tid]);
            CP_COMMIT();
        }
        uint2 nm0 = make_uint2(0,0), nm1 = make_uint2(0,0);
        if (more){ nm0 = mrow0[t+1]; nm1 = mrow1[t+1]; }

#pragma unroll
        for (int ks = 0; ks < 8; ks++){
            const int j0 = ks*8 + tig, j1 = j0 + 4;
            float4 jd0 = jd_s[buf][j0];
            float4 jd1 = jd_s[buf][j1];
            uint32 a0 = wcalc(f1_0, pq0, jd0, m0.x, m0.y, j0);
            uint32 a1 = wcalc(f1_1, pq1, jd0, m1.x, m1.y, j0);
            uint32 a2 = wcalc(f1_0, pq0, jd1, m0.x, m0.y, j1);
            uint32 a3 = wcalc(f1_1, pq1, jd1, m1.x, m1.y, j1);
            const float* hb0 = &h_B[buf][(ks*8 + tig)*76];
            const float* hb1 = hb0 + 4*76;
#pragma unroll
            for (int nt = 0; nt < 9; nt++){
                uint32 b0 = __float_as_uint(hb0[nt*8 + g]);
                uint32 b1 = __float_as_uint(hb1[nt*8 + g]);
                mma_tf32(acc[nt], a0, a1, a2, a3, b0, b1);
            }
        }
        if (more) CP_WAIT0();
        __syncthreads();
        buf ^= 1; m0 = nm0; m1 = nm1;
    }

    float* p0 = partp + (((size_t)head*gridDim.y + blockIdx.y)*NN + r0)*72;
    float* p1 = p0 + 8*72;
#pragma unroll
    for (int nt = 0; nt < 9; nt++){
        int c = nt*8 + 2*tig;
        if (c < 66){
            p0[c] = acc[nt].x; p1[c] = acc[nt].z;
            if (c + 1 < 66){ p0[c+1] = acc[nt].y; p1[c+1] = acc[nt].w; }
        }
    }
    if (tig == 1){ p0[66] = acc[8].x; p1[66] = acc[8].z; }
}

// combine S splits per head: out[row, head*66+c] = lrelu(num/den). blockDim = H*66.
__global__ void reduce_kernel(const float* __restrict__ part, int S,
                              float* __restrict__ out, int os)
{
    int i = blockIdx.x;
    int t = threadIdx.x;
    int h = t/66, c = t - h*66;
    const float* p = part + (((size_t)h*S)*NN + i)*72;
    float num = 0.f, den = 0.f;
    for (int s = 0; s < S; s++){
        num += p[c]; den += p[66];
        p += (size_t)NN*72;
    }
    float v = num/den;
    out[(size_t)i*os + h*66 + c] = fmaxf(v, 0.01f*v);
}

__global__ void __launch_bounds__(128) gate1_kernel(const float* __restrict__ sub,
    const float* __restrict__ hx, const float* __restrict__ W, const float* __restrict__ b,
    float* __restrict__ xout, float* __restrict__ uout)
{
    __shared__ float xs[66];
    int i = blockIdx.x, c = threadIdx.x;
    for (int k = c; k < 66; k += 128) xs[k] = sub[i*66+k];
    __syncthreads();
    float a = b[c];
    for (int k = 0; k < 66; k++) a += xs[k]*W[k*128+c];
    float v = 1.f/(1.f + __expf(-a));
    if (c < 64) xout[i*66 + 2 + c] = v*hx[i*64+c];
    else uout[i*64 + c - 64] = v;
}

__global__ void __launch_bounds__(64) final_kernel(const float* __restrict__ sub,
    const float* __restrict__ hx, const float* __restrict__ u,
    const float* __restrict__ W, const float* __restrict__ b, float* __restrict__ out)
{
    __shared__ float xs[66];
    int i = blockIdx.x, c = threadIdx.x;
    for (int k = c; k < 66; k += 64) xs[k] = sub[i*66+k];
    __syncthreads();
    float a = b[c];
    for (int k = 0; k < 66; k++) a += xs[k]*W[k*64+c];
    float t = tanhf(a);
    float uu = u[i*64+c];
    out[i*64+c] = uu*hx[i*64+c] + (1.f - uu)*t;
}

struct Ptrs {
    float *x,*h,*f1,*hcat,*sub,*u,*part;
    float2 *pq; float4 *jd; unsigned *mask;
};

static void run_subnet(const Ptrs& P, const float* W, const float* a1, const float* a2,
    const float* Wout, const float* ao1, const float* ao2)
{
    proj_kernel<64><<<dim3(64,4), 256>>>(P.x, 66, W, a1, a2, P.h, P.f1, P.pq, P.jd);
    agg_mma_kernel<<<dim3(32,2,4), 256>>>(P.h, P.f1, P.pq, P.jd, P.mask, P.part, 32);
    reduce_kernel<<<NN, 264>>>(P.part, 2, P.hcat, 264);
    proj_kernel<32><<<dim3(128,1), 256>>>(P.hcat, 264, Wout, ao1, ao2, P.h, P.f1, P.pq, P.jd);
    agg_mma_kernel<<<dim3(32,8,1), 256>>>(P.h, P.f1, P.pq, P.jd, P.mask, P.part, 8);
    reduce_kernel<<<NN, 66>>>(P.part, 8, P.sub, 66);
}

extern "C" void kernel_launch(void* const* d_in, const int* in_sizes, int n_in,
                              void* d_out, int out_size)
{
    const float* inputs = (const float*)d_in[0];
    const float* hx     = (const float*)d_in[1];
    const int*   adj    = (const int*)d_in[2];
    const float* m1_W   = (const float*)d_in[3];
    const float* m1_a1  = (const float*)d_in[4];
    const float* m1_a2  = (const float*)d_in[5];
    const float* m1_Wo  = (const float*)d_in[6];
    const float* m1_ao1 = (const float*)d_in[7];
    const float* m1_ao2 = (const float*)d_in[8];
    const float* m2_W   = (const float*)d_in[9];
    const float* m2_a1  = (const float*)d_in[10];
    const float* m2_a2  = (const float*)d_in[11];
    const float* m2_Wo  = (const float*)d_in[12];
    const float* m2_ao1 = (const float*)d_in[13];
    const float* m2_ao2 = (const float*)d_in[14];
    const float* g1_W   = (const float*)d_in[15];
    const float* g1_b   = (const float*)d_in[16];
    const float* g2_W   = (const float*)d_in[17];
    const float* g2_b   = (const float*)d_in[18];

    Ptrs P; void* t;
    cudaGetSymbolAddress(&t, g_x);    P.x = (float*)t;
    cudaGetSymbolAddress(&t, g_h);    P.h = (float*)t;
    cudaGetSymbolAddress(&t, g_f1);   P.f1 = (float*)t;
    cudaGetSymbolAddress(&t, g_pq);   P.pq = (float2*)t;
    cudaGetSymbolAddress(&t, g_jd);   P.jd = (float4*)t;
    cudaGetSymbolAddress(&t, g_hcat); P.hcat = (float*)t;
    cudaGetSymbolAddress(&t, g_sub);  P.sub = (float*)t;
    cudaGetSymbolAddress(&t, g_u);    P.u = (float*)t;
    cudaGetSymbolAddress(&t, g_part); P.part = (float*)t;
    cudaGetSymbolAddress(&t, g_mask); P.mask = (unsigned*)t;

    pack_mask_kernel<<<2048, 256>>>(adj, P.mask);
    build_x1_kernel<<<(NN*66+255)/256, 256>>>(inputs, hx, P.x);
    run_subnet(P, m1_W, m1_a1, m1_a2, m1_Wo, m1_ao1, m1_ao2);
    gate1_kernel<<<NN, 128>>>(P.sub, hx, g1_W, g1_b, P.x, P.u);
    run_subnet(P, m2_W, m2_a1, m2_a2, m2_Wo, m2_ao1, m2_ao2);
    final_kernel<<<NN, 64>>>(P.sub, hx, P.u, g2_W, g2_b, (float*)d_out);
}

// round 8
// speedup vs baseline: 5.0963x; 1.1953x over previous
#include <cuda_runtime.h>
#include <cstdint>

#define NN 4096
typedef unsigned long long ull;
typedef unsigned int uint32;

__device__ __align__(128) float  g_x[NN*66];
__device__ __align__(128) float  g_h[4*NN*80];
__device__ __align__(128) float  g_f1[4*NN];
__device__ __align__(128) float2 g_pq[4*NN];
__device__ __align__(128) float4 g_jd[4*NN];
__device__ __align__(128) float  g_hcat[NN*264];
__device__ __align__(128) float  g_sub[NN*66];
__device__ __align__(128) float  g_u[NN*64];
__device__ __align__(128) float  g_part[8UL*NN*72];
__device__ __align__(128) unsigned g_mask[NN*128];

__device__ __forceinline__ void cpa16(void* d, const void* s){
    unsigned sd = (unsigned)__cvta_generic_to_shared(d);
    asm volatile("cp.async.ca.shared.global [%0],[%1],16;" :: "r"(sd), "l"(s));
}
#define CP_COMMIT() asm volatile("cp.async.commit_group;")
#define CP_WAIT0()  asm volatile("cp.async.wait_group 0;")

__device__ __forceinline__ uint32 to_tf32(float f){
    uint32 u; asm("cvt.rna.tf32.f32 %0, %1;" : "=r"(u) : "f"(f)); return u;
}
__device__ __forceinline__ void mma_tf32(float4& d, uint32 a0, uint32 a1, uint32 a2, uint32 a3,
                                         uint32 b0, uint32 b1){
    asm("mma.sync.aligned.m16n8k8.row.col.f32.tf32.tf32.f32 "
        "{%0,%1,%2,%3},{%4,%5,%6,%7},{%8,%9},{%0,%1,%2,%3};"
        : "+f"(d.x), "+f"(d.y), "+f"(d.z), "+f"(d.w)
        : "r"(a0), "r"(a1), "r"(a2), "r"(a3), "r"(b0), "r"(b1));
}

__global__ void __launch_bounds__(256) pack_mask_kernel(const int* __restrict__ adj, unsigned* __restrict__ mask){
    int idx = blockIdx.x*256 + threadIdx.x;
    const int4* p = (const int4*)(adj + (size_t)idx*32);
    unsigned m = 0;
#pragma unroll
    for (int q = 0; q < 8; q++){
        int4 v = p[q];
        m |= (v.x>0?1u:0u)<<(q*4+0); m |= (v.y>0?1u:0u)<<(q*4+1);
        m |= (v.z>0?1u:0u)<<(q*4+2); m |= (v.w>0?1u:0u)<<(q*4+3);
    }
    mask[idx] = m;
}

__global__ void __launch_bounds__(256) build_x1_kernel(const float* __restrict__ inputs, const float* __restrict__ hx, float* __restrict__ x){
    int idx = blockIdx.x*256 + threadIdx.x;
    if (idx >= NN*66) return;
    int i = idx/66, c = idx - i*66;
    x[idx] = (c < 2) ? inputs[i*2+c] : hx[i*64 + c-2];
}

// h = x @ W per head (stride-80 out, tf32-rounded, col66=1) + f1/jd/pq epilogue.
template<int ROWS>
__global__ void __launch_bounds__(256) proj_kernel(const float* __restrict__ x, int Din,
    const float* __restrict__ W, const float* __restrict__ a1, const float* __restrict__ a2,
    float* __restrict__ ho, float* __restrict__ f1o, float2* __restrict__ pqo, float4* __restrict__ jdo)
{
    constexpr int PR = 256/ROWS;
    __shared__ float Ws[66*66];
    __shared__ float xs[ROWS*67];
    const int head = blockIdx.y;
    const int row0 = blockIdx.x*ROWS;
    const int tid = threadIdx.x;
    W += (size_t)head*Din*66; a1 += head*66; a2 += head*66;
    const int r = tid/PR, part = tid%PR;
    int c0, cnt;
    if (PR == 4){ c0 = (part<2)?part*17:34+(part-2)*16; cnt = (part<2)?17:16; }
    else        { c0 = (part<6)?part*9:54+(part-6)*6;   cnt = (part<6)?9:6; }
    float acc[17];
#pragma unroll
    for (int c = 0; c < 17; c++) acc[c] = 0.f;
    for (int k0 = 0; k0 < Din; k0 += 66){
        __syncthreads();
        for (int idx = tid; idx < 66*66; idx += 256) Ws[idx] = W[(size_t)k0*66 + idx];
        for (int idx = tid; idx < ROWS*66; idx += 256){
            int rr = idx/66, kk = idx - rr*66;
            xs[rr*67+kk] = x[(size_t)(row0+rr)*Din + k0 + kk];
        }
        __syncthreads();
        for (int kk = 0; kk < 66; kk++){
            float xv = xs[r*67+kk];
            const float* wr = Ws + kk*66 + c0;
#pragma unroll
            for (int c = 0; c < 17; c++) if (c < cnt) acc[c] += xv*wr[c];
        }
    }
    float p1 = 0.f, p2 = 0.f;
#pragma unroll
    for (int c = 0; c < 17; c++) if (c < cnt){ p1 += acc[c]*a1[c0+c]; p2 += acc[c]*a2[c0+c]; }
#pragma unroll
    for (int s = 1; s < PR; s <<= 1){
        p1 += __shfl_xor_sync(~0u, p1, s);
        p2 += __shfl_xor_sync(~0u, p2, s);
    }
    int row = row0 + r;
    if (part == 0){
        f1o[head*NN+row] = p1;
        pqo[head*NN+row] = make_float2(__expf(p1), __expf(0.2f*p1));
        jdo[head*NN+row] = make_float4(p2, __expf(p2), __expf(0.2f*p2), 0.f);
    }
    float* hr = ho + (size_t)(head*NN+row)*80;
#pragma unroll
    for (int c = 0; c < 17; c++) if (c < cnt) hr[c0+c] = __uint_as_float(to_tf32(acc[c]));
    if (part == PR-1){
        hr[66] = 1.0f;
#pragma unroll
        for (int c = 67; c < 80; c++) hr[c] = 0.f;
    }
}

__device__ __forceinline__ uint32 wcalc(float f1r, float2 pq, float4 jd, unsigned mx, unsigned my, int j){
    float xx = f1r + jd.x;
    float w = (xx > 0.f) ? pq.x*jd.y : pq.y*jd.z;
    unsigned wd = (j & 32) ? my : mx;
    w = ((wd >> (j & 31)) & 1u) ? w : 0.f;
    return to_tf32(w);
}

// tensor-core masked softmax-attention aggregation.
// 128 rows/block, 128 threads (4 warps), 32 rows per warp (two m16 tiles sharing B loads).
__global__ void __launch_bounds__(128) agg_mma_kernel(const float* __restrict__ hb,
    const float* __restrict__ f1b, const float2* __restrict__ pqb, const float4* __restrict__ jdb,
    const unsigned* __restrict__ mask, float* __restrict__ partp, int T)
{
    __shared__ float h_B[2][64*76];
    __shared__ float4 jd_s[2][64];
    const int head = blockIdx.z;
    const int row0 = blockIdx.x*128;
    const int tid = threadIdx.x;
    const int wid = tid>>5, lane = tid&31;
    const int g = lane>>2, tig = lane&3;
    const int t0 = blockIdx.y*T;
    const float* hsrc = hb + (size_t)head*NN*80;
    const float4* jds = jdb + head*NN;
    const int rA = row0 + wid*32 + g;          // rows: rA, rA+8, rA+16, rA+24
    const float f1_0 = f1b[head*NN + rA];
    const float f1_1 = f1b[head*NN + rA + 8];
    const float f1_2 = f1b[head*NN + rA + 16];
    const float f1_3 = f1b[head*NN + rA + 24];
    const float2 pq0 = pqb[head*NN + rA];
    const float2 pq1 = pqb[head*NN + rA + 8];
    const float2 pq2 = pqb[head*NN + rA + 16];
    const float2 pq3 = pqb[head*NN + rA + 24];
    const uint2* mrow0 = (const uint2*)(mask + (size_t)rA*128);
    const uint2* mrow1 = (const uint2*)(mask + (size_t)(rA+8)*128);
    const uint2* mrow2 = (const uint2*)(mask + (size_t)(rA+16)*128);
    const uint2* mrow3 = (const uint2*)(mask + (size_t)(rA+24)*128);

    float4 accA[9], accB[9];
#pragma unroll
    for (int nt = 0; nt < 9; nt++){ accA[nt] = make_float4(0.f,0.f,0.f,0.f); accB[nt] = accA[nt]; }

    // prefetch chunk t0 (1152 16B chunks, 128 threads -> 9 each)
#pragma unroll
    for (int i = 0; i < 9; i++){
        int idx = tid + i*128;
        int jr = idx/18, c4 = idx - jr*18;
        cpa16(&h_B[0][jr*76 + c4*4], hsrc + (size_t)(t0*64 + jr)*80 + c4*4);
    }
    if (tid < 64) cpa16(&jd_s[0][tid], &jds[t0*64 + tid]);
    CP_COMMIT();
    uint2 m0 = mrow0[t0], m1 = mrow1[t0], m2 = mrow2[t0], m3 = mrow3[t0];
    CP_WAIT0();
    __syncthreads();

    int buf = 0;
    for (int tt = 0; tt < T; tt++){
        const int t = t0 + tt;
        const bool more = (tt + 1 < T);
        if (more){
#pragma unroll
            for (int i = 0; i < 9; i++){
                int idx = tid + i*128;
                int jr = idx/18, c4 = idx - jr*18;
                cpa16(&h_B[buf^1][jr*76 + c4*4], hsrc + (size_t)((t+1)*64 + jr)*80 + c4*4);
            }
            if (tid < 64) cpa16(&jd_s[buf^1][tid], &jds[(t+1)*64 + tid]);
            CP_COMMIT();
        }
        uint2 nm0, nm1, nm2, nm3;
        if (more){ nm0 = mrow0[t+1]; nm1 = mrow1[t+1]; nm2 = mrow2[t+1]; nm3 = mrow3[t+1]; }

#pragma unroll
        for (int ks = 0; ks < 8; ks++){
            const int j0 = ks*8 + tig, j1 = j0 + 4;
            float4 jd0 = jd_s[buf][j0];
            float4 jd1 = jd_s[buf][j1];
            uint32 a0 = wcalc(f1_0, pq0, jd0, m0.x, m0.y, j0);
            uint32 a1 = wcalc(f1_1, pq1, jd0, m1.x, m1.y, j0);
            uint32 a2 = wcalc(f1_0, pq0, jd1, m0.x, m0.y, j1);
            uint32 a3 = wcalc(f1_1, pq1, jd1, m1.x, m1.y, j1);
            uint32 a4 = wcalc(f1_2, pq2, jd0, m2.x, m2.y, j0);
            uint32 a5 = wcalc(f1_3, pq3, jd0, m3.x, m3.y, j0);
            uint32 a6 = wcalc(f1_2, pq2, jd1, m2.x, m2.y, j1);
            uint32 a7 = wcalc(f1_3, pq3, jd1, m3.x, m3.y, j1);
            const float* hb0 = &h_B[buf][(ks*8 + tig)*76];
            const float* hb1 = hb0 + 4*76;
#pragma unroll
            for (int nt = 0; nt < 9; nt++){
                uint32 b0 = __float_as_uint(hb0[nt*8 + g]);
                uint32 b1 = __float_as_uint(hb1[nt*8 + g]);
                mma_tf32(accA[nt], a0, a1, a2, a3, b0, b1);
                mma_tf32(accB[nt], a4, a5, a6, a7, b0, b1);
            }
        }
        if (more) CP_WAIT0();
        __syncthreads();
        buf ^= 1;
        if (more){ m0 = nm0; m1 = nm1; m2 = nm2; m3 = nm3; }
    }

    float* p0 = partp + (((size_t)head*gridDim.y + blockIdx.y)*NN + rA)*72;
    float* p1 = p0 + 8*72;
    float* p2 = p0 + 16*72;
    float* p3 = p0 + 24*72;
#pragma unroll
    for (int nt = 0; nt < 9; nt++){
        int c = nt*8 + 2*tig;
        if (c < 66){
            p0[c] = accA[nt].x; p1[c] = accA[nt].z;
            p2[c] = accB[nt].x; p3[c] = accB[nt].z;
            if (c + 1 < 66){
                p0[c+1] = accA[nt].y; p1[c+1] = accA[nt].w;
                p2[c+1] = accB[nt].y; p3[c+1] = accB[nt].w;
            }
        }
    }
    if (tig == 1){
        p0[66] = accA[8].x; p1[66] = accA[8].z;
        p2[66] = accB[8].x; p3[66] = accB[8].z;
    }
}

// combine S splits per head: out[row, head*66+c] = lrelu(num/den). blockDim = H*66.
__global__ void reduce_kernel(const float* __restrict__ part, int S,
                              float* __restrict__ out, int os)
{
    int i = blockIdx.x;
    int t = threadIdx.x;
    int h = t/66, c = t - h*66;
    const float* p = part + (((size_t)h*S)*NN + i)*72;
    float num = 0.f, den = 0.f;
    for (int s = 0; s < S; s++){
        num += p[c]; den += p[66];
        p += (size_t)NN*72;
    }
    float v = num/den;
    out[(size_t)i*os + h*66 + c] = fmaxf(v, 0.01f*v);
}

__global__ void __launch_bounds__(128) gate1_kernel(const float* __restrict__ sub,
    const float* __restrict__ hx, const float* __restrict__ W, const float* __restrict__ b,
    float* __restrict__ xout, float* __restrict__ uout)
{
    __shared__ float xs[66];
    int i = blockIdx.x, c = threadIdx.x;
    for (int k = c; k < 66; k += 128) xs[k] = sub[i*66+k];
    __syncthreads();
    float a = b[c];
    for (int k = 0; k < 66; k++) a += xs[k]*W[k*128+c];
    float v = 1.f/(1.f + __expf(-a));
    if (c < 64) xout[i*66 + 2 + c] = v*hx[i*64+c];
    else uout[i*64 + c - 64] = v;
}

__global__ void __launch_bounds__(64) final_kernel(const float* __restrict__ sub,
    const float* __restrict__ hx, const float* __restrict__ u,
    const float* __restrict__ W, const float* __restrict__ b, float* __restrict__ out)
{
    __shared__ float xs[66];
    int i = blockIdx.x, c = threadIdx.x;
    for (int k = c; k < 66; k += 64) xs[k] = sub[i*66+k];
    __syncthreads();
    float a = b[c];
    for (int k = 0; k < 66; k++) a += xs[k]*W[k*64+c];
    float t = tanhf(a);
    float uu = u[i*64+c];
    out[i*64+c] = uu*hx[i*64+c] + (1.f - uu)*t;
}

struct Ptrs {
    float *x,*h,*f1,*hcat,*sub,*u,*part;
    float2 *pq; float4 *jd; unsigned *mask;
};

static void run_subnet(const Ptrs& P, const float* W, const float* a1, const float* a2,
    const float* Wout, const float* ao1, const float* ao2)
{
    proj_kernel<64><<<dim3(64,4), 256>>>(P.x, 66, W, a1, a2, P.h, P.f1, P.pq, P.jd);
    agg_mma_kernel<<<dim3(32,2,4), 128>>>(P.h, P.f1, P.pq, P.jd, P.mask, P.part, 32);
    reduce_kernel<<<NN, 264>>>(P.part, 2, P.hcat, 264);
    proj_kernel<32><<<dim3(128,1), 256>>>(P.hcat, 264, Wout, ao1, ao2, P.h, P.f1, P.pq, P.jd);
    agg_mma_kernel<<<dim3(32,8,1), 128>>>(P.h, P.f1, P.pq, P.jd, P.mask, P.part, 8);
    reduce_kernel<<<NN, 66>>>(P.part, 8, P.sub, 66);
}

extern "C" void kernel_launch(void* const* d_in, const int* in_sizes, int n_in,
                              void* d_out, int out_size)
{
    const float* inputs = (const float*)d_in[0];
    const float* hx     = (const float*)d_in[1];
    const int*   adj    = (const int*)d_in[2];
    const float* m1_W   = (const float*)d_in[3];
    const float* m1_a1  = (const float*)d_in[4];
    const float* m1_a2  = (const float*)d_in[5];
    const float* m1_Wo  = (const float*)d_in[6];
    const float* m1_ao1 = (const float*)d_in[7];
    const float* m1_ao2 = (const float*)d_in[8];
    const float* m2_W   = (const float*)d_in[9];
    const float* m2_a1  = (const float*)d_in[10];
    const float* m2_a2  = (const float*)d_in[11];
    const float* m2_Wo  = (const float*)d_in[12];
    const float* m2_ao1 = (const float*)d_in[13];
    const float* m2_ao2 = (const float*)d_in[14];
    const float* g1_W   = (const float*)d_in[15];
    const float* g1_b   = (const float*)d_in[16];
    const float* g2_W   = (const float*)d_in[17];
    const float* g2_b   = (const float*)d_in[18];

    Ptrs P; void* t;
    cudaGetSymbolAddress(&t, g_x);    P.x = (float*)t;
    cudaGetSymbolAddress(&t, g_h);    P.h = (float*)t;
    cudaGetSymbolAddress(&t, g_f1);   P.f1 = (float*)t;
    cudaGetSymbolAddress(&t, g_pq);   P.pq = (float2*)t;
    cudaGetSymbolAddress(&t, g_jd);   P.jd = (float4*)t;
    cudaGetSymbolAddress(&t, g_hcat); P.hcat = (float*)t;
    cudaGetSymbolAddress(&t, g_sub);  P.sub = (float*)t;
    cudaGetSymbolAddress(&t, g_u);    P.u = (float*)t;
    cudaGetSymbolAddress(&t, g_part); P.part = (float*)t;
    cudaGetSymbolAddress(&t, g_mask); P.mask = (unsigned*)t;

    pack_mask_kernel<<<2048, 256>>>(adj, P.mask);
    build_x1_kernel<<<(NN*66+255)/256, 256>>>(inputs, hx, P.x);
    run_subnet(P, m1_W, m1_a1, m1_a2, m1_Wo, m1_ao1, m1_ao2);
    gate1_kernel<<<NN, 128>>>(P.sub, hx, g1_W, g1_b, P.x, P.u);
    run_subnet(P, m2_W, m2_a1, m2_a2, m2_Wo, m2_ao1, m2_ao2);
    final_kernel<<<NN, 64>>>(P.sub, hx, P.u, g2_W, g2_b, (float*)d_out);
}

// round 9
// speedup vs baseline: 5.1469x; 1.0099x over previous
#include <cuda_runtime.h>
#include <cstdint>

#define NN 4096
typedef unsigned long long ull;
typedef unsigned int uint32;

__device__ __align__(128) float  g_x[NN*66];
__device__ __align__(128) float  g_h[4*NN*80];
__device__ __align__(128) float  g_f1[4*NN];
__device__ __align__(128) float2 g_pq[4*NN];
__device__ __align__(128) float4 g_jd[4*NN];
__device__ __align__(128) float  g_hcat[NN*264];
__device__ __align__(128) float  g_sub[NN*66];
__device__ __align__(128) float  g_u[NN*64];
__device__ __align__(128) float  g_part[16UL*NN*72];
__device__ __align__(128) unsigned g_mask[NN*128];

__device__ __forceinline__ void cpa16(void* d, const void* s){
    unsigned sd = (unsigned)__cvta_generic_to_shared(d);
    asm volatile("cp.async.ca.shared.global [%0],[%1],16;" :: "r"(sd), "l"(s));
}
#define CP_COMMIT() asm volatile("cp.async.commit_group;")
#define CP_WAIT0()  asm volatile("cp.async.wait_group 0;")

__device__ __forceinline__ uint32 to_tf32(float f){
    uint32 u; asm("cvt.rna.tf32.f32 %0, %1;" : "=r"(u) : "f"(f)); return u;
}
__device__ __forceinline__ void mma_tf32(float4& d, uint32 a0, uint32 a1, uint32 a2, uint32 a3,
                                         uint32 b0, uint32 b1){
    asm("mma.sync.aligned.m16n8k8.row.col.f32.tf32.tf32.f32 "
        "{%0,%1,%2,%3},{%4,%5,%6,%7},{%8,%9},{%0,%1,%2,%3};"
        : "+f"(d.x), "+f"(d.y), "+f"(d.z), "+f"(d.w)
        : "r"(a0), "r"(a1), "r"(a2), "r"(a3), "r"(b0), "r"(b1));
}

__global__ void __launch_bounds__(256) pack_mask_kernel(const int* __restrict__ adj, unsigned* __restrict__ mask){
    int idx = blockIdx.x*256 + threadIdx.x;
    const int4* p = (const int4*)(adj + (size_t)idx*32);
    unsigned m = 0;
#pragma unroll
    for (int q = 0; q < 8; q++){
        int4 v = p[q];
        m |= (v.x>0?1u:0u)<<(q*4+0); m |= (v.y>0?1u:0u)<<(q*4+1);
        m |= (v.z>0?1u:0u)<<(q*4+2); m |= (v.w>0?1u:0u)<<(q*4+3);
    }
    mask[idx] = m;
}

__global__ void __launch_bounds__(256) build_x1_kernel(const float* __restrict__ inputs, const float* __restrict__ hx, float* __restrict__ x){
    int idx = blockIdx.x*256 + threadIdx.x;
    if (idx >= NN*66) return;
    int i = idx/66, c = idx - i*66;
    x[idx] = (c < 2) ? inputs[i*2+c] : hx[i*64 + c-2];
}

// h = x @ W per head (stride-80 out, tf32-rounded, col66=1) + f1/jd/pq epilogue.
template<int ROWS>
__global__ void __launch_bounds__(256) proj_kernel(const float* __restrict__ x, int Din,
    const float* __restrict__ W, const float* __restrict__ a1, const float* __restrict__ a2,
    float* __restrict__ ho, float* __restrict__ f1o, float2* __restrict__ pqo, float4* __restrict__ jdo)
{
    constexpr int PR = 256/ROWS;
    __shared__ float Ws[66*66];
    __shared__ float xs[ROWS*67];
    const int head = blockIdx.y;
    const int row0 = blockIdx.x*ROWS;
    const int tid = threadIdx.x;
    W += (size_t)head*Din*66; a1 += head*66; a2 += head*66;
    const int r = tid/PR, part = tid%PR;
    int c0, cnt;
    if (PR == 4){ c0 = (part<2)?part*17:34+(part-2)*16; cnt = (part<2)?17:16; }
    else        { c0 = (part<6)?part*9:54+(part-6)*6;   cnt = (part<6)?9:6; }
    float acc[17];
#pragma unroll
    for (int c = 0; c < 17; c++) acc[c] = 0.f;
    for (int k0 = 0; k0 < Din; k0 += 66){
        __syncthreads();
        for (int idx = tid; idx < 66*66; idx += 256) Ws[idx] = W[(size_t)k0*66 + idx];
        for (int idx = tid; idx < ROWS*66; idx += 256){
            int rr = idx/66, kk = idx - rr*66;
            xs[rr*67+kk] = x[(size_t)(row0+rr)*Din + k0 + kk];
        }
        __syncthreads();
        for (int kk = 0; kk < 66; kk++){
            float xv = xs[r*67+kk];
            const float* wr = Ws + kk*66 + c0;
#pragma unroll
            for (int c = 0; c < 17; c++) if (c < cnt) acc[c] += xv*wr[c];
        }
    }
    float p1 = 0.f, p2 = 0.f;
#pragma unroll
    for (int c = 0; c < 17; c++) if (c < cnt){ p1 += acc[c]*a1[c0+c]; p2 += acc[c]*a2[c0+c]; }
#pragma unroll
    for (int s = 1; s < PR; s <<= 1){
        p1 += __shfl_xor_sync(~0u, p1, s);
        p2 += __shfl_xor_sync(~0u, p2, s);
    }
    int row = row0 + r;
    if (part == 0){
        f1o[head*NN+row] = p1;
        pqo[head*NN+row] = make_float2(__expf(p1), __expf(0.2f*p1));
        jdo[head*NN+row] = make_float4(p2, __expf(p2), __expf(0.2f*p2), 0.f);
    }
    float* hr = ho + (size_t)(head*NN+row)*80;
#pragma unroll
    for (int c = 0; c < 17; c++) if (c < cnt) hr[c0+c] = __uint_as_float(to_tf32(acc[c]));
    if (part == PR-1){
        hr[66] = 1.0f;
#pragma unroll
        for (int c = 67; c < 80; c++) hr[c] = 0.f;
    }
}

// A-fragment weight: fp32 bits passed straight to mma (HW truncates to tf32).
__device__ __forceinline__ uint32 wcalc(float f1r, float2 pq, float4 jd, unsigned mx, unsigned my, int j){
    float xx = f1r + jd.x;
    float w = (xx > 0.f) ? pq.x*jd.y : pq.y*jd.z;
    unsigned wd = (j & 32) ? my : mx;
    w = ((wd >> (j & 31)) & 1u) ? w : 0.f;
    return __float_as_uint(w);
}

// tensor-core masked softmax-attention aggregation.
// 128 rows/block, 128 threads (4 warps), 32 rows per warp (two m16 tiles sharing B loads).
__global__ void __launch_bounds__(128) agg_mma_kernel(const float* __restrict__ hb,
    const float* __restrict__ f1b, const float2* __restrict__ pqb, const float4* __restrict__ jdb,
    const unsigned* __restrict__ mask, float* __restrict__ partp, int T)
{
    __shared__ float h_B[2][64*76];
    __shared__ float4 jd_s[2][64];
    const int head = blockIdx.z;
    const int row0 = blockIdx.x*128;
    const int tid = threadIdx.x;
    const int wid = tid>>5, lane = tid&31;
    const int g = lane>>2, tig = lane&3;
    const int t0 = blockIdx.y*T;
    const float* hsrc = hb + (size_t)head*NN*80;
    const float4* jds = jdb + head*NN;
    const int rA = row0 + wid*32 + g;          // rows: rA, rA+8, rA+16, rA+24
    const float f1_0 = f1b[head*NN + rA];
    const float f1_1 = f1b[head*NN + rA + 8];
    const float f1_2 = f1b[head*NN + rA + 16];
    const float f1_3 = f1b[head*NN + rA + 24];
    const float2 pq0 = pqb[head*NN + rA];
    const float2 pq1 = pqb[head*NN + rA + 8];
    const float2 pq2 = pqb[head*NN + rA + 16];
    const float2 pq3 = pqb[head*NN + rA + 24];
    const uint2* mrow0 = (const uint2*)(mask + (size_t)rA*128);
    const uint2* mrow1 = (const uint2*)(mask + (size_t)(rA+8)*128);
    const uint2* mrow2 = (const uint2*)(mask + (size_t)(rA+16)*128);
    const uint2* mrow3 = (const uint2*)(mask + (size_t)(rA+24)*128);

    float4 accA[9], accB[9];
#pragma unroll
    for (int nt = 0; nt < 9; nt++){ accA[nt] = make_float4(0.f,0.f,0.f,0.f); accB[nt] = accA[nt]; }

    // prefetch chunk t0 (1152 16B chunks, 128 threads -> 9 each)
#pragma unroll
    for (int i = 0; i < 9; i++){
        int idx = tid + i*128;
        int jr = idx/18, c4 = idx - jr*18;
        cpa16(&h_B[0][jr*76 + c4*4], hsrc + (size_t)(t0*64 + jr)*80 + c4*4);
    }
    if (tid < 64) cpa16(&jd_s[0][tid], &jds[t0*64 + tid]);
    CP_COMMIT();
    uint2 m0 = mrow0[t0], m1 = mrow1[t0], m2 = mrow2[t0], m3 = mrow3[t0];
    CP_WAIT0();
    __syncthreads();

    int buf = 0;
    for (int tt = 0; tt < T; tt++){
        const int t = t0 + tt;
        const bool more = (tt + 1 < T);
        if (more){
#pragma unroll
            for (int i = 0; i < 9; i++){
                int idx = tid + i*128;
                int jr = idx/18, c4 = idx - jr*18;
                cpa16(&h_B[buf^1][jr*76 + c4*4], hsrc + (size_t)((t+1)*64 + jr)*80 + c4*4);
            }
            if (tid < 64) cpa16(&jd_s[buf^1][tid], &jds[(t+1)*64 + tid]);
            CP_COMMIT();
        }
        uint2 nm0, nm1, nm2, nm3;
        if (more){ nm0 = mrow0[t+1]; nm1 = mrow1[t+1]; nm2 = mrow2[t+1]; nm3 = mrow3[t+1]; }

#pragma unroll
        for (int ks = 0; ks < 8; ks++){
            const int j0 = ks*8 + tig, j1 = j0 + 4;
            float4 jd0 = jd_s[buf][j0];
            float4 jd1 = jd_s[buf][j1];
            uint32 a0 = wcalc(f1_0, pq0, jd0, m0.x, m0.y, j0);
            uint32 a1 = wcalc(f1_1, pq1, jd0, m1.x, m1.y, j0);
            uint32 a2 = wcalc(f1_0, pq0, jd1, m0.x, m0.y, j1);
            uint32 a3 = wcalc(f1_1, pq1, jd1, m1.x, m1.y, j1);
            uint32 a4 = wcalc(f1_2, pq2, jd0, m2.x, m2.y, j0);
            uint32 a5 = wcalc(f1_3, pq3, jd0, m3.x, m3.y, j0);
            uint32 a6 = wcalc(f1_2, pq2, jd1, m2.x, m2.y, j1);
            uint32 a7 = wcalc(f1_3, pq3, jd1, m3.x, m3.y, j1);
            const float* hb0 = &h_B[buf][(ks*8 + tig)*76];
            const float* hb1 = hb0 + 4*76;
#pragma unroll
            for (int nt = 0; nt < 9; nt++){
                uint32 b0 = __float_as_uint(hb0[nt*8 + g]);
                uint32 b1 = __float_as_uint(hb1[nt*8 + g]);
                mma_tf32(accA[nt], a0, a1, a2, a3, b0, b1);
                mma_tf32(accB[nt], a4, a5, a6, a7, b0, b1);
            }
        }
        if (more) CP_WAIT0();
        __syncthreads();
        buf ^= 1;
        if (more){ m0 = nm0; m1 = nm1; m2 = nm2; m3 = nm3; }
    }

    float* p0 = partp + (((size_t)head*gridDim.y + blockIdx.y)*NN + rA)*72;
    float* p1 = p0 + 8*72;
    float* p2 = p0 + 16*72;
    float* p3 = p0 + 24*72;
#pragma unroll
    for (int nt = 0; nt < 9; nt++){
        int c = nt*8 + 2*tig;
        if (c < 66){
            p0[c] = accA[nt].x; p1[c] = accA[nt].z;
            p2[c] = accB[nt].x; p3[c] = accB[nt].z;
            if (c + 1 < 66){
                p0[c+1] = accA[nt].y; p1[c+1] = accA[nt].w;
                p2[c+1] = accB[nt].y; p3[c+1] = accB[nt].w;
            }
        }
    }
    if (tig == 1){
        p0[66] = accA[8].x; p1[66] = accA[8].z;
        p2[66] = accB[8].x; p3[66] = accB[8].z;
    }
}

// combine S splits per head: out[row, head*66+c] = lrelu(num/den). blockDim = H*66.
__global__ void reduce_kernel(const float* __restrict__ part, int S,
                              float* __restrict__ out, int os)
{
    int i = blockIdx.x;
    int t = threadIdx.x;
    int h = t/66, c = t - h*66;
    const float* p = part + (((size_t)h*S)*NN + i)*72;
    float num = 0.f, den = 0.f;
    for (int s = 0; s < S; s++){
        num += p[c]; den += p[66];
        p += (size_t)NN*72;
    }
    float v = num/den;
    out[(size_t)i*os + h*66 + c] = fmaxf(v, 0.01f*v);
}

__global__ void __launch_bounds__(128) gate1_kernel(const float* __restrict__ sub,
    const float* __restrict__ hx, const float* __restrict__ W, const float* __restrict__ b,
    float* __restrict__ xout, float* __restrict__ uout)
{
    __shared__ float xs[66];
    int i = blockIdx.x, c = threadIdx.x;
    for (int k = c; k < 66; k += 128) xs[k] = sub[i*66+k];
    __syncthreads();
    float a = b[c];
    for (int k = 0; k < 66; k++) a += xs[k]*W[k*128+c];
    float v = 1.f/(1.f + __expf(-a));
    if (c < 64) xout[i*66 + 2 + c] = v*hx[i*64+c];
    else uout[i*64 + c - 64] = v;
}

__global__ void __launch_bounds__(64) final_kernel(const float* __restrict__ sub,
    const float* __restrict__ hx, const float* __restrict__ u,
    const float* __restrict__ W, const float* __restrict__ b, float* __restrict__ out)
{
    __shared__ float xs[66];
    int i = blockIdx.x, c = threadIdx.x;
    for (int k = c; k < 66; k += 64) xs[k] = sub[i*66+k];
    __syncthreads();
    float a = b[c];
    for (int k = 0; k < 66; k++) a += xs[k]*W[k*64+c];
    float t = tanhf(a);
    float uu = u[i*64+c];
    out[i*64+c] = uu*hx[i*64+c] + (1.f - uu)*t;
}

struct Ptrs {
    float *x,*h,*f1,*hcat,*sub,*u,*part;
    float2 *pq; float4 *jd; unsigned *mask;
};

static void run_subnet(const Ptrs& P, const float* W, const float* a1, const float* a2,
    const float* Wout, const float* ao1, const float* ao2)
{
    proj_kernel<64><<<dim3(64,4), 256>>>(P.x, 66, W, a1, a2, P.h, P.f1, P.pq, P.jd);
    agg_mma_kernel<<<dim3(32,4,4), 128>>>(P.h, P.f1, P.pq, P.jd, P.mask, P.part, 16);
    reduce_kernel<<<NN, 264>>>(P.part, 4, P.hcat, 264);
    proj_kernel<32><<<dim3(128,1), 256>>>(P.hcat, 264, Wout, ao1, ao2, P.h, P.f1, P.pq, P.jd);
    agg_mma_kernel<<<dim3(32,16,1), 128>>>(P.h, P.f1, P.pq, P.jd, P.mask, P.part, 4);
    reduce_kernel<<<NN, 66>>>(P.part, 16, P.sub, 66);
}

extern "C" void kernel_launch(void* const* d_in, const int* in_sizes, int n_in,
                              void* d_out, int out_size)
{
    const float* inputs = (const float*)d_in[0];
    const float* hx     = (const float*)d_in[1];
    const int*   adj    = (const int*)d_in[2];
    const float* m1_W   = (const float*)d_in[3];
    const float* m1_a1  = (const float*)d_in[4];
    const float* m1_a2  = (const float*)d_in[5];
    const float* m1_Wo  = (const float*)d_in[6];
    const float* m1_ao1 = (const float*)d_in[7];
    const float* m1_ao2 = (const float*)d_in[8];
    const float* m2_W   = (const float*)d_in[9];
    const float* m2_a1  = (const float*)d_in[10];
    const float* m2_a2  = (const float*)d_in[11];
    const float* m2_Wo  = (const float*)d_in[12];
    const float* m2_ao1 = (const float*)d_in[13];
    const float* m2_ao2 = (const float*)d_in[14];
    const float* g1_W   = (const float*)d_in[15];
    const float* g1_b   = (const float*)d_in[16];
    const float* g2_W   = (const float*)d_in[17];
    const float* g2_b   = (const float*)d_in[18];

    Ptrs P; void* t;
    cudaGetSymbolAddress(&t, g_x);    P.x = (float*)t;
    cudaGetSymbolAddress(&t, g_h);    P.h = (float*)t;
    cudaGetSymbolAddress(&t, g_f1);   P.f1 = (float*)t;
    cudaGetSymbolAddress(&t, g_pq);   P.pq = (float2*)t;
    cudaGetSymbolAddress(&t, g_jd);   P.jd = (float4*)t;
    cudaGetSymbolAddress(&t, g_hcat); P.hcat = (float*)t;
    cudaGetSymbolAddress(&t, g_sub);  P.sub = (float*)t;
    cudaGetSymbolAddress(&t, g_u);    P.u = (float*)t;
    cudaGetSymbolAddress(&t, g_part); P.part = (float*)t;
    cudaGetSymbolAddress(&t, g_mask); P.mask = (unsigned*)t;

    pack_mask_kernel<<<2048, 256>>>(adj, P.mask);
    build_x1_kernel<<<(NN*66+255)/256, 256>>>(inputs, hx, P.x);
    run_subnet(P, m1_W, m1_a1, m1_a2, m1_Wo, m1_ao1, m1_ao2);
    gate1_kernel<<<NN, 128>>>(P.sub, hx, g1_W, g1_b, P.x, P.u);
    run_subnet(P, m2_W, m2_a1, m2_a2, m2_Wo, m2_ao1, m2_ao2);
    final_kernel<<<NN, 64>>>(P.sub, hx, P.u, g2_W, g2_b, (float*)d_out);
}